// round 8
// baseline (speedup 1.0000x reference)
#include <cuda_runtime.h>

#define N_NODES 50000
#define N_EDGES 800000
#define D       96
#define H2      32
#define OUTD    4
#define CH      (D/4)        // 24 float4 chunks per row
#define SCAN_B  1024
#define SCAN_NB ((N_NODES + SCAN_B - 1) / SCAN_B)   // 49

// Scratch (no allocations allowed)
__device__ float g_z1[N_NODES * D];
__device__ float g_h1[N_NODES * D];
__device__ float g_y2[N_NODES * H2];
__device__ float g_z2[N_NODES * H2];
__device__ int   g_deg[N_NODES];
__device__ int   g_rowptr[N_NODES + 1];
__device__ int   g_cursor[N_NODES];
__device__ int   g_bsum[SCAN_NB];
__device__ int   g_ebuf[N_EDGES];

// ---------------- CSR build (parallel scan, R4-proven) ----------------

__global__ void k_hist(const int* __restrict__ ei, int* __restrict__ deg) {
    int e = blockIdx.x * blockDim.x + threadIdx.x;
    if (e < N_EDGES) atomicAdd(&deg[ei[N_EDGES + e]], 1);
}

__global__ __launch_bounds__(SCAN_B)
void k_scan1(const int* __restrict__ deg, int* __restrict__ rowptr, int* __restrict__ bsum) {
    __shared__ int s[SCAN_B];
    int t = threadIdx.x;
    int i = blockIdx.x * SCAN_B + t;
    int v = (i < N_NODES) ? deg[i] : 0;
    s[t] = v;
    __syncthreads();
    for (int off = 1; off < SCAN_B; off <<= 1) {
        int add = (t >= off) ? s[t - off] : 0;
        __syncthreads();
        s[t] += add;
        __syncthreads();
    }
    if (i < N_NODES) rowptr[i] = s[t] - v;
    if (t == SCAN_B - 1) bsum[blockIdx.x] = s[t];
}

__global__ void k_scan2(int* __restrict__ bsum) {
    __shared__ int s[64];
    int t = threadIdx.x;
    int v = (t < SCAN_NB) ? bsum[t] : 0;
    s[t] = v;
    __syncthreads();
    for (int off = 1; off < 64; off <<= 1) {
        int add = (t >= off) ? s[t - off] : 0;
        __syncthreads();
        s[t] += add;
        __syncthreads();
    }
    if (t < SCAN_NB) bsum[t] = s[t] - v;
}

__global__ __launch_bounds__(SCAN_B)
void k_scan3(int* __restrict__ rowptr, const int* __restrict__ bsum, int* __restrict__ cursor) {
    int i = blockIdx.x * SCAN_B + threadIdx.x;
    if (i < N_NODES) {
        int r = rowptr[i] + bsum[blockIdx.x];
        rowptr[i] = r;
        cursor[i] = r;
    }
    if (i == 0) rowptr[N_NODES] = N_EDGES;
}

__global__ void k_fill(const int* __restrict__ ei, int* __restrict__ cursor,
                       int* __restrict__ ebuf) {
    int e = blockIdx.x * blockDim.x + threadIdx.x;
    if (e < N_EDGES) {
        int dst = ei[N_EDGES + e];
        int pos = atomicAdd(&cursor[dst], 1);
        ebuf[pos] = ei[e];
    }
}

// ---------------- fused scale + gather (96-dim, warp per node) ----------------
__global__ __launch_bounds__(256)
void k_gagg(const float* __restrict__ feat, const float* __restrict__ eps,
            const int* __restrict__ rowptr, const int* __restrict__ ebuf,
            float* __restrict__ z) {
    int warp = (blockIdx.x * blockDim.x + threadIdx.x) >> 5;
    int lane = threadIdx.x & 31;
    if (warp >= N_NODES) return;
    int beg = rowptr[warp];
    int end = rowptr[warp + 1];
    const float4* f4 = reinterpret_cast<const float4*>(feat);
    float4 acc = make_float4(0.f, 0.f, 0.f, 0.f);
    if (lane < CH) {
        float s = 1.0f + *eps;
        float4 v = f4[warp * CH + lane];
        acc.x = s * v.x; acc.y = s * v.y; acc.z = s * v.z; acc.w = s * v.w;
    }
    int e = beg;
    for (; e + 4 <= end; e += 4) {
        int s0 = __ldg(&ebuf[e + 0]);
        int s1 = __ldg(&ebuf[e + 1]);
        int s2 = __ldg(&ebuf[e + 2]);
        int s3 = __ldg(&ebuf[e + 3]);
        if (lane < CH) {
            float4 v0 = f4[s0 * CH + lane];
            float4 v1 = f4[s1 * CH + lane];
            float4 v2 = f4[s2 * CH + lane];
            float4 v3 = f4[s3 * CH + lane];
            acc.x += v0.x + v1.x + v2.x + v3.x;
            acc.y += v0.y + v1.y + v2.y + v3.y;
            acc.z += v0.z + v1.z + v2.z + v3.z;
            acc.w += v0.w + v1.w + v2.w + v3.w;
        }
    }
    for (; e < end; e++) {
        int src = __ldg(&ebuf[e]);
        if (lane < CH) {
            float4 v = f4[src * CH + lane];
            acc.x += v.x; acc.y += v.y; acc.z += v.z; acc.w += v.w;
        }
    }
    if (lane < CH) reinterpret_cast<float4*>(z)[warp * CH + lane] = acc;
}

// ---------------- gather in 32-dim space (8 lanes per node) ----------------
__global__ __launch_bounds__(256)
void k_gagg32(const float* __restrict__ y2, const float* __restrict__ eps,
              const int* __restrict__ rowptr, const int* __restrict__ ebuf,
              float* __restrict__ z) {
    int t = blockIdx.x * blockDim.x + threadIdx.x;
    int node = t >> 3;
    int c = t & 7;
    if (node >= N_NODES) return;
    int beg = rowptr[node];
    int end = rowptr[node + 1];
    const float4* f4 = reinterpret_cast<const float4*>(y2);
    float s = 1.0f + *eps;
    float4 v = f4[node * 8 + c];
    float4 acc = make_float4(s * v.x, s * v.y, s * v.z, s * v.w);
    int e = beg;
    for (; e + 4 <= end; e += 4) {
        int s0 = __ldg(&ebuf[e + 0]);
        int s1 = __ldg(&ebuf[e + 1]);
        int s2 = __ldg(&ebuf[e + 2]);
        int s3 = __ldg(&ebuf[e + 3]);
        float4 v0 = f4[s0 * 8 + c];
        float4 v1 = f4[s1 * 8 + c];
        float4 v2 = f4[s2 * 8 + c];
        float4 v3 = f4[s3 * 8 + c];
        acc.x += v0.x + v1.x + v2.x + v3.x;
        acc.y += v0.y + v1.y + v2.y + v3.y;
        acc.z += v0.z + v1.z + v2.z + v3.z;
        acc.w += v0.w + v1.w + v2.w + v3.w;
    }
    for (; e < end; e++) {
        int src = __ldg(&ebuf[e]);
        float4 w = f4[src * 8 + c];
        acc.x += w.x; acc.y += w.y; acc.z += w.z; acc.w += w.w;
    }
    reinterpret_cast<float4*>(z)[node * 8 + c] = acc;
}

// ---------------- MLP1 (exact R4 version, writes h) ----------------
#define M1   64
__global__ __launch_bounds__(192)
void k_mlp1(const float* __restrict__ z,
            const float* __restrict__ W1a, const float* __restrict__ b1a,
            const float* __restrict__ W1b, const float* __restrict__ b1b,
            float* __restrict__ h) {
    __shared__ float zs[M1 * 97];
    __shared__ float Wm[48 * 96];
    const int tid = threadIdx.x;
    const int cg = tid % 24;
    const int rg = tid / 24;
    const int c0 = cg * 4;
    const int r0 = rg * 8;
    const int row0 = blockIdx.x * M1;

    for (int i = tid; i < M1 * CH; i += 192) {
        int r = i / CH, kc = i % CH;
        float4 v = (row0 + r < N_NODES)
                 ? reinterpret_cast<const float4*>(z)[(row0 + r) * CH + kc]
                 : make_float4(0.f, 0.f, 0.f, 0.f);
        zs[r * 97 + kc * 4 + 0] = v.x;
        zs[r * 97 + kc * 4 + 1] = v.y;
        zs[r * 97 + kc * 4 + 2] = v.z;
        zs[r * 97 + kc * 4 + 3] = v.w;
    }

    float4 bias = *reinterpret_cast<const float4*>(&b1a[c0]);
    float acc[8][4];
    #pragma unroll
    for (int i = 0; i < 8; i++) {
        acc[i][0] = bias.x; acc[i][1] = bias.y; acc[i][2] = bias.z; acc[i][3] = bias.w;
    }

    for (int kh = 0; kh < 2; kh++) {
        __syncthreads();
        for (int i = tid; i < 48 * 96 / 4; i += 192)
            reinterpret_cast<float4*>(Wm)[i] =
                reinterpret_cast<const float4*>(W1a + kh * 48 * 96)[i];
        __syncthreads();
        #pragma unroll 4
        for (int k = 0; k < 48; k++) {
            int kg = kh * 48 + k;
            float4 w = *reinterpret_cast<float4*>(&Wm[k * 96 + c0]);
            #pragma unroll
            for (int i = 0; i < 8; i++) {
                float zv = zs[(r0 + i) * 97 + kg];
                acc[i][0] = fmaf(zv, w.x, acc[i][0]);
                acc[i][1] = fmaf(zv, w.y, acc[i][1]);
                acc[i][2] = fmaf(zv, w.z, acc[i][2]);
                acc[i][3] = fmaf(zv, w.w, acc[i][3]);
            }
        }
    }
    __syncthreads();
    #pragma unroll
    for (int i = 0; i < 8; i++) {
        zs[(r0 + i) * 97 + c0 + 0] = fmaxf(acc[i][0], 0.f);
        zs[(r0 + i) * 97 + c0 + 1] = fmaxf(acc[i][1], 0.f);
        zs[(r0 + i) * 97 + c0 + 2] = fmaxf(acc[i][2], 0.f);
        zs[(r0 + i) * 97 + c0 + 3] = fmaxf(acc[i][3], 0.f);
    }

    bias = *reinterpret_cast<const float4*>(&b1b[c0]);
    #pragma unroll
    for (int i = 0; i < 8; i++) {
        acc[i][0] = bias.x; acc[i][1] = bias.y; acc[i][2] = bias.z; acc[i][3] = bias.w;
    }
    for (int kh = 0; kh < 2; kh++) {
        __syncthreads();
        for (int i = tid; i < 48 * 96 / 4; i += 192)
            reinterpret_cast<float4*>(Wm)[i] =
                reinterpret_cast<const float4*>(W1b + kh * 48 * 96)[i];
        __syncthreads();
        #pragma unroll 4
        for (int k = 0; k < 48; k++) {
            int kg = kh * 48 + k;
            float4 w = *reinterpret_cast<float4*>(&Wm[k * 96 + c0]);
            #pragma unroll
            for (int i = 0; i < 8; i++) {
                float tv = zs[(r0 + i) * 97 + kg];
                acc[i][0] = fmaf(tv, w.x, acc[i][0]);
                acc[i][1] = fmaf(tv, w.y, acc[i][1]);
                acc[i][2] = fmaf(tv, w.z, acc[i][2]);
                acc[i][3] = fmaf(tv, w.w, acc[i][3]);
            }
        }
    }
    #pragma unroll
    for (int i = 0; i < 8; i++) {
        int row = row0 + r0 + i;
        if (row < N_NODES) {
            float4 o;
            o.x = fmaxf(acc[i][0], 0.f);
            o.y = fmaxf(acc[i][1], 0.f);
            o.z = fmaxf(acc[i][2], 0.f);
            o.w = fmaxf(acc[i][3], 0.f);
            *reinterpret_cast<float4*>(&h[(long long)row * D + c0]) = o;
        }
    }
}

// ---------------- y2 = h @ W2a (no bias; pre-aggregation) ----------------
// 64 rows/block, 256 threads: thread tile 2 rows x 4 cols.
#define MY 64
__global__ __launch_bounds__(256)
void k_y2(const float* __restrict__ h, const float* __restrict__ W2a,
          float* __restrict__ y2) {
    __shared__ float hs[MY * 97];      // 24832 B
    __shared__ float Wm[D * H2];       // 12288 B
    const int tid = threadIdx.x;
    const int cg = tid % 8;            // 8 col groups of 4
    const int rg = tid / 8;            // 0..31 row groups of 2
    const int cb = cg * 4;
    const int rb = rg * 2;
    const int row0 = blockIdx.x * MY;

    for (int i = tid; i < D * H2 / 4; i += 256)
        reinterpret_cast<float4*>(Wm)[i] = reinterpret_cast<const float4*>(W2a)[i];
    for (int i = tid; i < MY * CH; i += 256) {
        int r = i / CH, kc = i % CH;
        float4 v = (row0 + r < N_NODES)
                 ? reinterpret_cast<const float4*>(h)[(row0 + r) * CH + kc]
                 : make_float4(0.f, 0.f, 0.f, 0.f);
        hs[r * 97 + kc * 4 + 0] = v.x;
        hs[r * 97 + kc * 4 + 1] = v.y;
        hs[r * 97 + kc * 4 + 2] = v.z;
        hs[r * 97 + kc * 4 + 3] = v.w;
    }
    __syncthreads();

    float a0[4] = {0.f, 0.f, 0.f, 0.f};
    float a1[4] = {0.f, 0.f, 0.f, 0.f};
    #pragma unroll 8
    for (int k = 0; k < D; k++) {
        float4 w = *reinterpret_cast<float4*>(&Wm[k * H2 + cb]);
        float h0 = hs[(rb + 0) * 97 + k];
        float h1 = hs[(rb + 1) * 97 + k];
        a0[0] = fmaf(h0, w.x, a0[0]); a0[1] = fmaf(h0, w.y, a0[1]);
        a0[2] = fmaf(h0, w.z, a0[2]); a0[3] = fmaf(h0, w.w, a0[3]);
        a1[0] = fmaf(h1, w.x, a1[0]); a1[1] = fmaf(h1, w.y, a1[1]);
        a1[2] = fmaf(h1, w.z, a1[2]); a1[3] = fmaf(h1, w.w, a1[3]);
    }
    int r0g = row0 + rb;
    if (r0g < N_NODES)
        *reinterpret_cast<float4*>(&y2[(long long)r0g * H2 + cb]) =
            make_float4(a0[0], a0[1], a0[2], a0[3]);
    if (r0g + 1 < N_NODES)
        *reinterpret_cast<float4*>(&y2[(long long)(r0g + 1) * H2 + cb]) =
            make_float4(a1[0], a1[1], a1[2], a1[3]);
}

// ---------------- MLP2 tail: a=relu(z2+b2a); b=relu(a@W2b+b2b); out=b@Wh+bh
__global__ __launch_bounds__(256)
void k_mlp2(const float* __restrict__ z2,
            const float* __restrict__ b2a, const float* __restrict__ W2b,
            const float* __restrict__ b2b, const float* __restrict__ Wh,
            const float* __restrict__ bh, float* __restrict__ out) {
    __shared__ float W2b_s[H2 * H2];
    __shared__ float Wh_s[H2 * OUTD];
    __shared__ float b2a_s[H2];
    __shared__ float b2b_s[H2];
    const int tid = threadIdx.x;
    for (int i = tid; i < H2 * H2 / 4; i += 256)
        reinterpret_cast<float4*>(W2b_s)[i] = reinterpret_cast<const float4*>(W2b)[i];
    if (tid < H2 * OUTD) Wh_s[tid] = Wh[tid];
    if (tid < H2) { b2a_s[tid] = b2a[tid]; b2b_s[tid] = b2b[tid]; }
    __syncthreads();

    int row = blockIdx.x * 256 + tid;
    if (row >= N_NODES) return;

    float a[H2];
    const float4* zr = reinterpret_cast<const float4*>(z2 + (long long)row * H2);
    #pragma unroll
    for (int c = 0; c < 8; c++) {
        float4 v = zr[c];
        a[c * 4 + 0] = fmaxf(v.x + b2a_s[c * 4 + 0], 0.f);
        a[c * 4 + 1] = fmaxf(v.y + b2a_s[c * 4 + 1], 0.f);
        a[c * 4 + 2] = fmaxf(v.z + b2a_s[c * 4 + 2], 0.f);
        a[c * 4 + 3] = fmaxf(v.w + b2a_s[c * 4 + 3], 0.f);
    }
    float o0 = bh[0], o1 = bh[1], o2 = bh[2], o3 = bh[3];
    #pragma unroll 4
    for (int j = 0; j < H2; j++) {
        float bj = b2b_s[j];
        #pragma unroll
        for (int k = 0; k < H2; k++) bj = fmaf(a[k], W2b_s[k * H2 + j], bj);
        bj = fmaxf(bj, 0.f);
        o0 = fmaf(bj, Wh_s[j * OUTD + 0], o0);
        o1 = fmaf(bj, Wh_s[j * OUTD + 1], o1);
        o2 = fmaf(bj, Wh_s[j * OUTD + 2], o2);
        o3 = fmaf(bj, Wh_s[j * OUTD + 3], o3);
    }
    *reinterpret_cast<float4*>(&out[(long long)row * OUTD]) =
        make_float4(o0, o1, o2, o3);
}

extern "C" void kernel_launch(void* const* d_in, const int* in_sizes, int n_in,
                              void* d_out, int out_size) {
    const float* x    = (const float*)d_in[0];
    const int*   ei   = (const int*)  d_in[1];
    const float* eps1 = (const float*)d_in[2];
    const float* eps2 = (const float*)d_in[3];
    const float* W1a  = (const float*)d_in[4];
    const float* b1a  = (const float*)d_in[5];
    const float* W1b  = (const float*)d_in[6];
    const float* b1b  = (const float*)d_in[7];
    const float* W2a  = (const float*)d_in[8];
    const float* b2a  = (const float*)d_in[9];
    const float* W2b  = (const float*)d_in[10];
    const float* b2b  = (const float*)d_in[11];
    const float* Wh   = (const float*)d_in[12];
    const float* bh   = (const float*)d_in[13];
    float* out = (float*)d_out;

    float *z1, *h1, *y2, *z2;
    int *deg, *rowptr, *cursor, *bsum, *ebuf;
    cudaGetSymbolAddress((void**)&z1, g_z1);
    cudaGetSymbolAddress((void**)&h1, g_h1);
    cudaGetSymbolAddress((void**)&y2, g_y2);
    cudaGetSymbolAddress((void**)&z2, g_z2);
    cudaGetSymbolAddress((void**)&deg, g_deg);
    cudaGetSymbolAddress((void**)&rowptr, g_rowptr);
    cudaGetSymbolAddress((void**)&cursor, g_cursor);
    cudaGetSymbolAddress((void**)&bsum, g_bsum);
    cudaGetSymbolAddress((void**)&ebuf, g_ebuf);

    const int eb = (N_EDGES + 255) / 256;
    const int gagg_blocks   = (N_NODES * 32 + 255) / 256;
    const int gagg32_blocks = (N_NODES * 8 + 255) / 256;
    const int mlp1_blocks   = (N_NODES + M1 - 1) / M1;
    const int y2_blocks     = (N_NODES + MY - 1) / MY;
    const int mlp2_blocks   = (N_NODES + 255) / 256;

    // CSR build (parallel scan, 6 launches — measured cheap in R4)
    cudaMemsetAsync(deg, 0, N_NODES * sizeof(int));
    k_hist<<<eb, 256>>>(ei, deg);
    k_scan1<<<SCAN_NB, SCAN_B>>>(deg, rowptr, bsum);
    k_scan2<<<1, 64>>>(bsum);
    k_scan3<<<SCAN_NB, SCAN_B>>>(rowptr, bsum, cursor);
    k_fill<<<eb, 256>>>(ei, cursor, ebuf);

    // Layer 1
    k_gagg<<<gagg_blocks, 256>>>(x, eps1, rowptr, ebuf, z1);
    k_mlp1<<<mlp1_blocks, 192>>>(z1, W1a, b1a, W1b, b1b, h1);

    // Layer 2: project to 32-dim first, aggregate there
    k_y2<<<y2_blocks, 256>>>(h1, W2a, y2);
    k_gagg32<<<gagg32_blocks, 256>>>(y2, eps2, rowptr, ebuf, z2);
    k_mlp2<<<mlp2_blocks, 256>>>(z2, b2a, W2b, b2b, Wh, bh, out);
}

// round 9
// speedup vs baseline: 1.3498x; 1.3498x over previous
#include <cuda_runtime.h>

#define N_NODES 50000
#define N_EDGES 800000
#define D       96
#define H2      32
#define OUTD    4
#define CH      (D/4)        // 24 float4 chunks per row
#define SCAN_B  1024
#define SCAN_NB ((N_NODES + SCAN_B - 1) / SCAN_B)   // 49

// Scratch (no allocations allowed)
__device__ float g_z1[N_NODES * D];
__device__ float g_h1[N_NODES * D];
__device__ float g_z2[N_NODES * D];
__device__ int   g_deg[N_NODES];
__device__ int   g_rowptr[N_NODES + 1];
__device__ int   g_cursor[N_NODES];
__device__ int   g_bsum[SCAN_NB];
__device__ int   g_ebuf[N_EDGES];

// ---------------- CSR build ----------------

__global__ void k_hist(const int* __restrict__ ei, int* __restrict__ deg) {
    int e = blockIdx.x * blockDim.x + threadIdx.x;
    if (e < N_EDGES) atomicAdd(&deg[ei[N_EDGES + e]], 1);
}

__global__ __launch_bounds__(SCAN_B)
void k_scan1(const int* __restrict__ deg, int* __restrict__ rowptr, int* __restrict__ bsum) {
    __shared__ int s[SCAN_B];
    int t = threadIdx.x;
    int i = blockIdx.x * SCAN_B + t;
    int v = (i < N_NODES) ? deg[i] : 0;
    s[t] = v;
    __syncthreads();
    for (int off = 1; off < SCAN_B; off <<= 1) {
        int add = (t >= off) ? s[t - off] : 0;
        __syncthreads();
        s[t] += add;
        __syncthreads();
    }
    if (i < N_NODES) rowptr[i] = s[t] - v;
    if (t == SCAN_B - 1) bsum[blockIdx.x] = s[t];
}

__global__ void k_scan2(int* __restrict__ bsum) {
    __shared__ int s[64];
    int t = threadIdx.x;
    int v = (t < SCAN_NB) ? bsum[t] : 0;
    s[t] = v;
    __syncthreads();
    for (int off = 1; off < 64; off <<= 1) {
        int add = (t >= off) ? s[t - off] : 0;
        __syncthreads();
        s[t] += add;
        __syncthreads();
    }
    if (t < SCAN_NB) bsum[t] = s[t] - v;
}

__global__ __launch_bounds__(SCAN_B)
void k_scan3(int* __restrict__ rowptr, const int* __restrict__ bsum, int* __restrict__ cursor) {
    int i = blockIdx.x * SCAN_B + threadIdx.x;
    if (i < N_NODES) {
        int r = rowptr[i] + bsum[blockIdx.x];
        rowptr[i] = r;
        cursor[i] = r;
    }
    if (i == 0) rowptr[N_NODES] = N_EDGES;
}

__global__ void k_fill(const int* __restrict__ ei, int* __restrict__ cursor,
                       int* __restrict__ ebuf) {
    int e = blockIdx.x * blockDim.x + threadIdx.x;
    if (e < N_EDGES) {
        int dst = ei[N_EDGES + e];
        int pos = atomicAdd(&cursor[dst], 1);
        ebuf[pos] = ei[e];
    }
}

// ---------------- fused scale + gather (96-dim, warp per node) ----------------
// 8-wide edge unroll: doubles outstanding independent loads (latency-bound per ncu).
__global__ __launch_bounds__(256)
void k_gagg(const float* __restrict__ feat, const float* __restrict__ eps,
            const int* __restrict__ rowptr, const int* __restrict__ ebuf,
            float* __restrict__ z) {
    int warp = (blockIdx.x * blockDim.x + threadIdx.x) >> 5;
    int lane = threadIdx.x & 31;
    if (warp >= N_NODES) return;
    int beg = rowptr[warp];
    int end = rowptr[warp + 1];
    const float4* f4 = reinterpret_cast<const float4*>(feat);
    float4 acc = make_float4(0.f, 0.f, 0.f, 0.f);
    if (lane < CH) {
        float s = 1.0f + *eps;
        float4 v = f4[warp * CH + lane];
        acc.x = s * v.x; acc.y = s * v.y; acc.z = s * v.z; acc.w = s * v.w;
    }
    int e = beg;
    for (; e + 8 <= end; e += 8) {
        int s0 = __ldg(&ebuf[e + 0]);
        int s1 = __ldg(&ebuf[e + 1]);
        int s2 = __ldg(&ebuf[e + 2]);
        int s3 = __ldg(&ebuf[e + 3]);
        int s4 = __ldg(&ebuf[e + 4]);
        int s5 = __ldg(&ebuf[e + 5]);
        int s6 = __ldg(&ebuf[e + 6]);
        int s7 = __ldg(&ebuf[e + 7]);
        if (lane < CH) {
            float4 v0 = f4[s0 * CH + lane];
            float4 v1 = f4[s1 * CH + lane];
            float4 v2 = f4[s2 * CH + lane];
            float4 v3 = f4[s3 * CH + lane];
            float4 v4 = f4[s4 * CH + lane];
            float4 v5 = f4[s5 * CH + lane];
            float4 v6 = f4[s6 * CH + lane];
            float4 v7 = f4[s7 * CH + lane];
            acc.x += (v0.x + v1.x) + (v2.x + v3.x) + ((v4.x + v5.x) + (v6.x + v7.x));
            acc.y += (v0.y + v1.y) + (v2.y + v3.y) + ((v4.y + v5.y) + (v6.y + v7.y));
            acc.z += (v0.z + v1.z) + (v2.z + v3.z) + ((v4.z + v5.z) + (v6.z + v7.z));
            acc.w += (v0.w + v1.w) + (v2.w + v3.w) + ((v4.w + v5.w) + (v6.w + v7.w));
        }
    }
    for (; e + 4 <= end; e += 4) {
        int s0 = __ldg(&ebuf[e + 0]);
        int s1 = __ldg(&ebuf[e + 1]);
        int s2 = __ldg(&ebuf[e + 2]);
        int s3 = __ldg(&ebuf[e + 3]);
        if (lane < CH) {
            float4 v0 = f4[s0 * CH + lane];
            float4 v1 = f4[s1 * CH + lane];
            float4 v2 = f4[s2 * CH + lane];
            float4 v3 = f4[s3 * CH + lane];
            acc.x += (v0.x + v1.x) + (v2.x + v3.x);
            acc.y += (v0.y + v1.y) + (v2.y + v3.y);
            acc.z += (v0.z + v1.z) + (v2.z + v3.z);
            acc.w += (v0.w + v1.w) + (v2.w + v3.w);
        }
    }
    for (; e < end; e++) {
        int src = __ldg(&ebuf[e]);
        if (lane < CH) {
            float4 v = f4[src * CH + lane];
            acc.x += v.x; acc.y += v.y; acc.z += v.z; acc.w += v.w;
        }
    }
    if (lane < CH) reinterpret_cast<float4*>(z)[warp * CH + lane] = acc;
}

// ---------------- MLP1: register-tiled (exact R4) ----------------
#define M1   64
__global__ __launch_bounds__(192)
void k_mlp1(const float* __restrict__ z,
            const float* __restrict__ W1a, const float* __restrict__ b1a,
            const float* __restrict__ W1b, const float* __restrict__ b1b,
            float* __restrict__ h) {
    __shared__ float zs[M1 * 97];
    __shared__ float Wm[48 * 96];
    const int tid = threadIdx.x;
    const int cg = tid % 24;
    const int rg = tid / 24;
    const int c0 = cg * 4;
    const int r0 = rg * 8;
    const int row0 = blockIdx.x * M1;

    for (int i = tid; i < M1 * CH; i += 192) {
        int r = i / CH, kc = i % CH;
        float4 v = (row0 + r < N_NODES)
                 ? reinterpret_cast<const float4*>(z)[(row0 + r) * CH + kc]
                 : make_float4(0.f, 0.f, 0.f, 0.f);
        zs[r * 97 + kc * 4 + 0] = v.x;
        zs[r * 97 + kc * 4 + 1] = v.y;
        zs[r * 97 + kc * 4 + 2] = v.z;
        zs[r * 97 + kc * 4 + 3] = v.w;
    }

    float4 bias = *reinterpret_cast<const float4*>(&b1a[c0]);
    float acc[8][4];
    #pragma unroll
    for (int i = 0; i < 8; i++) {
        acc[i][0] = bias.x; acc[i][1] = bias.y; acc[i][2] = bias.z; acc[i][3] = bias.w;
    }

    for (int kh = 0; kh < 2; kh++) {
        __syncthreads();
        for (int i = tid; i < 48 * 96 / 4; i += 192)
            reinterpret_cast<float4*>(Wm)[i] =
                reinterpret_cast<const float4*>(W1a + kh * 48 * 96)[i];
        __syncthreads();
        #pragma unroll 4
        for (int k = 0; k < 48; k++) {
            int kg = kh * 48 + k;
            float4 w = *reinterpret_cast<float4*>(&Wm[k * 96 + c0]);
            #pragma unroll
            for (int i = 0; i < 8; i++) {
                float zv = zs[(r0 + i) * 97 + kg];
                acc[i][0] = fmaf(zv, w.x, acc[i][0]);
                acc[i][1] = fmaf(zv, w.y, acc[i][1]);
                acc[i][2] = fmaf(zv, w.z, acc[i][2]);
                acc[i][3] = fmaf(zv, w.w, acc[i][3]);
            }
        }
    }
    __syncthreads();
    #pragma unroll
    for (int i = 0; i < 8; i++) {
        zs[(r0 + i) * 97 + c0 + 0] = fmaxf(acc[i][0], 0.f);
        zs[(r0 + i) * 97 + c0 + 1] = fmaxf(acc[i][1], 0.f);
        zs[(r0 + i) * 97 + c0 + 2] = fmaxf(acc[i][2], 0.f);
        zs[(r0 + i) * 97 + c0 + 3] = fmaxf(acc[i][3], 0.f);
    }

    bias = *reinterpret_cast<const float4*>(&b1b[c0]);
    #pragma unroll
    for (int i = 0; i < 8; i++) {
        acc[i][0] = bias.x; acc[i][1] = bias.y; acc[i][2] = bias.z; acc[i][3] = bias.w;
    }
    for (int kh = 0; kh < 2; kh++) {
        __syncthreads();
        for (int i = tid; i < 48 * 96 / 4; i += 192)
            reinterpret_cast<float4*>(Wm)[i] =
                reinterpret_cast<const float4*>(W1b + kh * 48 * 96)[i];
        __syncthreads();
        #pragma unroll 4
        for (int k = 0; k < 48; k++) {
            int kg = kh * 48 + k;
            float4 w = *reinterpret_cast<float4*>(&Wm[k * 96 + c0]);
            #pragma unroll
            for (int i = 0; i < 8; i++) {
                float tv = zs[(r0 + i) * 97 + kg];
                acc[i][0] = fmaf(tv, w.x, acc[i][0]);
                acc[i][1] = fmaf(tv, w.y, acc[i][1]);
                acc[i][2] = fmaf(tv, w.z, acc[i][2]);
                acc[i][3] = fmaf(tv, w.w, acc[i][3]);
            }
        }
    }
    #pragma unroll
    for (int i = 0; i < 8; i++) {
        int row = row0 + r0 + i;
        if (row < N_NODES) {
            float4 o;
            o.x = fmaxf(acc[i][0], 0.f);
            o.y = fmaxf(acc[i][1], 0.f);
            o.z = fmaxf(acc[i][2], 0.f);
            o.w = fmaxf(acc[i][3], 0.f);
            *reinterpret_cast<float4*>(&h[(long long)row * D + c0]) = o;
        }
    }
}

// ---------------- MLP2 + head: register-tiled (exact R4) ----------------
#define M2 64
__global__ __launch_bounds__(128)
void k_mlp2(const float* __restrict__ z2,
            const float* __restrict__ W2a, const float* __restrict__ b2a,
            const float* __restrict__ W2b, const float* __restrict__ b2b,
            const float* __restrict__ Wh,  const float* __restrict__ bh,
            float* __restrict__ out) {
    __shared__ float zs[M2 * 97];
    __shared__ float W2a_s[D * H2];
    __shared__ float W2b_s[H2 * H2];
    __shared__ float Wh_s[H2 * OUTD];
    float* t_s = zs;
    float* b_s = zs + M2 * 33;

    const int tid = threadIdx.x;
    const int cg = tid % 8;
    const int rg = tid / 8;
    const int c0 = cg * 4;
    const int r0 = rg * 4;
    const int row0 = blockIdx.x * M2;

    for (int i = tid; i < D * H2 / 4;    i += 128)
        reinterpret_cast<float4*>(W2a_s)[i] = reinterpret_cast<const float4*>(W2a)[i];
    for (int i = tid; i < H2 * H2 / 4;   i += 128)
        reinterpret_cast<float4*>(W2b_s)[i] = reinterpret_cast<const float4*>(W2b)[i];
    for (int i = tid; i < H2 * OUTD; i += 128) Wh_s[i] = Wh[i];
    for (int i = tid; i < M2 * CH; i += 128) {
        int r = i / CH, kc = i % CH;
        float4 v = (row0 + r < N_NODES)
                 ? reinterpret_cast<const float4*>(z2)[(row0 + r) * CH + kc]
                 : make_float4(0.f, 0.f, 0.f, 0.f);
        zs[r * 97 + kc * 4 + 0] = v.x;
        zs[r * 97 + kc * 4 + 1] = v.y;
        zs[r * 97 + kc * 4 + 2] = v.z;
        zs[r * 97 + kc * 4 + 3] = v.w;
    }
    __syncthreads();

    float4 bias = *reinterpret_cast<const float4*>(&b2a[c0]);
    float acc[4][4];
    #pragma unroll
    for (int i = 0; i < 4; i++) {
        acc[i][0] = bias.x; acc[i][1] = bias.y; acc[i][2] = bias.z; acc[i][3] = bias.w;
    }
    #pragma unroll 4
    for (int k = 0; k < D; k++) {
        float4 w = *reinterpret_cast<float4*>(&W2a_s[k * H2 + c0]);
        #pragma unroll
        for (int i = 0; i < 4; i++) {
            float zv = zs[(r0 + i) * 97 + k];
            acc[i][0] = fmaf(zv, w.x, acc[i][0]);
            acc[i][1] = fmaf(zv, w.y, acc[i][1]);
            acc[i][2] = fmaf(zv, w.z, acc[i][2]);
            acc[i][3] = fmaf(zv, w.w, acc[i][3]);
        }
    }
    __syncthreads();
    #pragma unroll
    for (int i = 0; i < 4; i++) {
        t_s[(r0 + i) * 33 + c0 + 0] = fmaxf(acc[i][0], 0.f);
        t_s[(r0 + i) * 33 + c0 + 1] = fmaxf(acc[i][1], 0.f);
        t_s[(r0 + i) * 33 + c0 + 2] = fmaxf(acc[i][2], 0.f);
        t_s[(r0 + i) * 33 + c0 + 3] = fmaxf(acc[i][3], 0.f);
    }
    __syncthreads();

    bias = *reinterpret_cast<const float4*>(&b2b[c0]);
    #pragma unroll
    for (int i = 0; i < 4; i++) {
        acc[i][0] = bias.x; acc[i][1] = bias.y; acc[i][2] = bias.z; acc[i][3] = bias.w;
    }
    #pragma unroll 4
    for (int k = 0; k < H2; k++) {
        float4 w = *reinterpret_cast<float4*>(&W2b_s[k * H2 + c0]);
        #pragma unroll
        for (int i = 0; i < 4; i++) {
            float tv = t_s[(r0 + i) * 33 + k];
            acc[i][0] = fmaf(tv, w.x, acc[i][0]);
            acc[i][1] = fmaf(tv, w.y, acc[i][1]);
            acc[i][2] = fmaf(tv, w.z, acc[i][2]);
            acc[i][3] = fmaf(tv, w.w, acc[i][3]);
        }
    }
    __syncthreads();
    #pragma unroll
    for (int i = 0; i < 4; i++) {
        b_s[(r0 + i) * 33 + c0 + 0] = fmaxf(acc[i][0], 0.f);
        b_s[(r0 + i) * 33 + c0 + 1] = fmaxf(acc[i][1], 0.f);
        b_s[(r0 + i) * 33 + c0 + 2] = fmaxf(acc[i][2], 0.f);
        b_s[(r0 + i) * 33 + c0 + 3] = fmaxf(acc[i][3], 0.f);
    }
    __syncthreads();

    if (tid < M2) {
        int row = row0 + tid;
        if (row < N_NODES) {
            float o0 = bh[0], o1 = bh[1], o2 = bh[2], o3 = bh[3];
            #pragma unroll
            for (int k = 0; k < H2; k++) {
                float bv = b_s[tid * 33 + k];
                o0 = fmaf(bv, Wh_s[k * OUTD + 0], o0);
                o1 = fmaf(bv, Wh_s[k * OUTD + 1], o1);
                o2 = fmaf(bv, Wh_s[k * OUTD + 2], o2);
                o3 = fmaf(bv, Wh_s[k * OUTD + 3], o3);
            }
            float4 o = make_float4(o0, o1, o2, o3);
            *reinterpret_cast<float4*>(&out[(long long)row * OUTD]) = o;
        }
    }
}

extern "C" void kernel_launch(void* const* d_in, const int* in_sizes, int n_in,
                              void* d_out, int out_size) {
    const float* x    = (const float*)d_in[0];
    const int*   ei   = (const int*)  d_in[1];
    const float* eps1 = (const float*)d_in[2];
    const float* eps2 = (const float*)d_in[3];
    const float* W1a  = (const float*)d_in[4];
    const float* b1a  = (const float*)d_in[5];
    const float* W1b  = (const float*)d_in[6];
    const float* b1b  = (const float*)d_in[7];
    const float* W2a  = (const float*)d_in[8];
    const float* b2a  = (const float*)d_in[9];
    const float* W2b  = (const float*)d_in[10];
    const float* b2b  = (const float*)d_in[11];
    const float* Wh   = (const float*)d_in[12];
    const float* bh   = (const float*)d_in[13];
    float* out = (float*)d_out;

    float *z1, *h1, *z2;
    int *deg, *rowptr, *cursor, *bsum, *ebuf;
    cudaGetSymbolAddress((void**)&z1, g_z1);
    cudaGetSymbolAddress((void**)&h1, g_h1);
    cudaGetSymbolAddress((void**)&z2, g_z2);
    cudaGetSymbolAddress((void**)&deg, g_deg);
    cudaGetSymbolAddress((void**)&rowptr, g_rowptr);
    cudaGetSymbolAddress((void**)&cursor, g_cursor);
    cudaGetSymbolAddress((void**)&bsum, g_bsum);
    cudaGetSymbolAddress((void**)&ebuf, g_ebuf);

    const int eb = (N_EDGES + 255) / 256;
    const int gagg_blocks = (N_NODES * 32 + 255) / 256;
    const int mlp1_blocks = (N_NODES + M1 - 1) / M1;
    const int mlp2_blocks = (N_NODES + M2 - 1) / M2;

    // CSR build (once, shared by both layers)
    cudaMemsetAsync(deg, 0, N_NODES * sizeof(int));
    k_hist<<<eb, 256>>>(ei, deg);
    k_scan1<<<SCAN_NB, SCAN_B>>>(deg, rowptr, bsum);
    k_scan2<<<1, 64>>>(bsum);
    k_scan3<<<SCAN_NB, SCAN_B>>>(rowptr, bsum, cursor);
    k_fill<<<eb, 256>>>(ei, cursor, ebuf);

    // Layer 1
    k_gagg<<<gagg_blocks, 256>>>(x, eps1, rowptr, ebuf, z1);
    k_mlp1<<<mlp1_blocks, 192>>>(z1, W1a, b1a, W1b, b1b, h1);

    // Layer 2 (full 96-dim aggregation — the empirically fast path)
    k_gagg<<<gagg_blocks, 256>>>(h1, eps2, rowptr, ebuf, z2);
    k_mlp2<<<mlp2_blocks, 128>>>(z2, W2a, b2a, W2b, b2b, Wh, bh, out);
}

// round 10
// speedup vs baseline: 1.3796x; 1.0221x over previous
#include <cuda_runtime.h>
#include <cuda_fp16.h>

#define N_NODES 50000
#define N_EDGES 800000
#define D       96
#define H2      32
#define OUTD    4
#define CH      (D/4)        // 24 chunks per row (float4 for fp32, half4 for fp16)
#define SCAN_B  1024
#define SCAN_NB ((N_NODES + SCAN_B - 1) / SCAN_B)   // 49

// Scratch (no allocations allowed)
__device__ float  g_z1[N_NODES * D];
__device__ float  g_z2[N_NODES * D];
__device__ __half g_x16[N_NODES * D];
__device__ __half g_h16[N_NODES * D];
__device__ int    g_deg[N_NODES];
__device__ int    g_rowptr[N_NODES + 1];
__device__ int    g_cursor[N_NODES];
__device__ int    g_bsum[SCAN_NB];
__device__ int    g_ebuf[N_EDGES];

// ---------------- CSR build (R4-proven) ----------------

__global__ void k_hist(const int* __restrict__ ei, int* __restrict__ deg) {
    int e = blockIdx.x * blockDim.x + threadIdx.x;
    if (e < N_EDGES) atomicAdd(&deg[ei[N_EDGES + e]], 1);
}

__global__ __launch_bounds__(SCAN_B)
void k_scan1(const int* __restrict__ deg, int* __restrict__ rowptr, int* __restrict__ bsum) {
    __shared__ int s[SCAN_B];
    int t = threadIdx.x;
    int i = blockIdx.x * SCAN_B + t;
    int v = (i < N_NODES) ? deg[i] : 0;
    s[t] = v;
    __syncthreads();
    for (int off = 1; off < SCAN_B; off <<= 1) {
        int add = (t >= off) ? s[t - off] : 0;
        __syncthreads();
        s[t] += add;
        __syncthreads();
    }
    if (i < N_NODES) rowptr[i] = s[t] - v;
    if (t == SCAN_B - 1) bsum[blockIdx.x] = s[t];
}

__global__ void k_scan2(int* __restrict__ bsum) {
    __shared__ int s[64];
    int t = threadIdx.x;
    int v = (t < SCAN_NB) ? bsum[t] : 0;
    s[t] = v;
    __syncthreads();
    for (int off = 1; off < 64; off <<= 1) {
        int add = (t >= off) ? s[t - off] : 0;
        __syncthreads();
        s[t] += add;
        __syncthreads();
    }
    if (t < SCAN_NB) bsum[t] = s[t] - v;
}

__global__ __launch_bounds__(SCAN_B)
void k_scan3(int* __restrict__ rowptr, const int* __restrict__ bsum, int* __restrict__ cursor) {
    int i = blockIdx.x * SCAN_B + threadIdx.x;
    if (i < N_NODES) {
        int r = rowptr[i] + bsum[blockIdx.x];
        rowptr[i] = r;
        cursor[i] = r;
    }
    if (i == 0) rowptr[N_NODES] = N_EDGES;
}

__global__ void k_fill(const int* __restrict__ ei, int* __restrict__ cursor,
                       int* __restrict__ ebuf) {
    int e = blockIdx.x * blockDim.x + threadIdx.x;
    if (e < N_EDGES) {
        int dst = ei[N_EDGES + e];
        int pos = atomicAdd(&cursor[dst], 1);
        ebuf[pos] = ei[e];
    }
}

// ---------------- x -> fp16 convert ----------------
__global__ void k_cvt(const float* __restrict__ x, __half* __restrict__ x16, int n4) {
    int i = blockIdx.x * blockDim.x + threadIdx.x;
    if (i < n4) {
        float4 v = reinterpret_cast<const float4*>(x)[i];
        __half2 p0 = __floats2half2_rn(v.x, v.y);
        __half2 p1 = __floats2half2_rn(v.z, v.w);
        uint2 st;
        st.x = *reinterpret_cast<unsigned*>(&p0);
        st.y = *reinterpret_cast<unsigned*>(&p1);
        reinterpret_cast<uint2*>(x16)[i] = st;
    }
}

// ---------------- fused scale + gather from fp16 (warp per node) ----------------
__device__ __forceinline__ float4 h4_to_f4(uint2 r) {
    __half2 h0 = *reinterpret_cast<__half2*>(&r.x);
    __half2 h1 = *reinterpret_cast<__half2*>(&r.y);
    float2 a = __half22float2(h0);
    float2 b = __half22float2(h1);
    return make_float4(a.x, a.y, b.x, b.y);
}

__global__ __launch_bounds__(256)
void k_gagg_h(const __half* __restrict__ feat, const float* __restrict__ eps,
              const int* __restrict__ rowptr, const int* __restrict__ ebuf,
              float* __restrict__ z) {
    int warp = (blockIdx.x * blockDim.x + threadIdx.x) >> 5;
    int lane = threadIdx.x & 31;
    if (warp >= N_NODES) return;
    int beg = rowptr[warp];
    int end = rowptr[warp + 1];
    const uint2* f2 = reinterpret_cast<const uint2*>(feat);
    float4 acc = make_float4(0.f, 0.f, 0.f, 0.f);
    if (lane < CH) {
        float s = 1.0f + *eps;
        float4 v = h4_to_f4(f2[warp * CH + lane]);
        acc.x = s * v.x; acc.y = s * v.y; acc.z = s * v.z; acc.w = s * v.w;
    }
    int e = beg;
    for (; e + 4 <= end; e += 4) {
        int s0 = __ldg(&ebuf[e + 0]);
        int s1 = __ldg(&ebuf[e + 1]);
        int s2 = __ldg(&ebuf[e + 2]);
        int s3 = __ldg(&ebuf[e + 3]);
        if (lane < CH) {
            float4 v0 = h4_to_f4(f2[s0 * CH + lane]);
            float4 v1 = h4_to_f4(f2[s1 * CH + lane]);
            float4 v2 = h4_to_f4(f2[s2 * CH + lane]);
            float4 v3 = h4_to_f4(f2[s3 * CH + lane]);
            acc.x += (v0.x + v1.x) + (v2.x + v3.x);
            acc.y += (v0.y + v1.y) + (v2.y + v3.y);
            acc.z += (v0.z + v1.z) + (v2.z + v3.z);
            acc.w += (v0.w + v1.w) + (v2.w + v3.w);
        }
    }
    for (; e < end; e++) {
        int src = __ldg(&ebuf[e]);
        if (lane < CH) {
            float4 v = h4_to_f4(f2[src * CH + lane]);
            acc.x += v.x; acc.y += v.y; acc.z += v.z; acc.w += v.w;
        }
    }
    if (lane < CH) reinterpret_cast<float4*>(z)[warp * CH + lane] = acc;
}

// ---------------- MLP1: register-tiled (R4), h written as fp16 ----------------
#define M1   64
__global__ __launch_bounds__(192)
void k_mlp1(const float* __restrict__ z,
            const float* __restrict__ W1a, const float* __restrict__ b1a,
            const float* __restrict__ W1b, const float* __restrict__ b1b,
            __half* __restrict__ h) {
    __shared__ float zs[M1 * 97];
    __shared__ float Wm[48 * 96];
    const int tid = threadIdx.x;
    const int cg = tid % 24;
    const int rg = tid / 24;
    const int c0 = cg * 4;
    const int r0 = rg * 8;
    const int row0 = blockIdx.x * M1;

    for (int i = tid; i < M1 * CH; i += 192) {
        int r = i / CH, kc = i % CH;
        float4 v = (row0 + r < N_NODES)
                 ? reinterpret_cast<const float4*>(z)[(row0 + r) * CH + kc]
                 : make_float4(0.f, 0.f, 0.f, 0.f);
        zs[r * 97 + kc * 4 + 0] = v.x;
        zs[r * 97 + kc * 4 + 1] = v.y;
        zs[r * 97 + kc * 4 + 2] = v.z;
        zs[r * 97 + kc * 4 + 3] = v.w;
    }

    float4 bias = *reinterpret_cast<const float4*>(&b1a[c0]);
    float acc[8][4];
    #pragma unroll
    for (int i = 0; i < 8; i++) {
        acc[i][0] = bias.x; acc[i][1] = bias.y; acc[i][2] = bias.z; acc[i][3] = bias.w;
    }

    for (int kh = 0; kh < 2; kh++) {
        __syncthreads();
        for (int i = tid; i < 48 * 96 / 4; i += 192)
            reinterpret_cast<float4*>(Wm)[i] =
                reinterpret_cast<const float4*>(W1a + kh * 48 * 96)[i];
        __syncthreads();
        #pragma unroll 4
        for (int k = 0; k < 48; k++) {
            int kg = kh * 48 + k;
            float4 w = *reinterpret_cast<float4*>(&Wm[k * 96 + c0]);
            #pragma unroll
            for (int i = 0; i < 8; i++) {
                float zv = zs[(r0 + i) * 97 + kg];
                acc[i][0] = fmaf(zv, w.x, acc[i][0]);
                acc[i][1] = fmaf(zv, w.y, acc[i][1]);
                acc[i][2] = fmaf(zv, w.z, acc[i][2]);
                acc[i][3] = fmaf(zv, w.w, acc[i][3]);
            }
        }
    }
    __syncthreads();
    #pragma unroll
    for (int i = 0; i < 8; i++) {
        zs[(r0 + i) * 97 + c0 + 0] = fmaxf(acc[i][0], 0.f);
        zs[(r0 + i) * 97 + c0 + 1] = fmaxf(acc[i][1], 0.f);
        zs[(r0 + i) * 97 + c0 + 2] = fmaxf(acc[i][2], 0.f);
        zs[(r0 + i) * 97 + c0 + 3] = fmaxf(acc[i][3], 0.f);
    }

    bias = *reinterpret_cast<const float4*>(&b1b[c0]);
    #pragma unroll
    for (int i = 0; i < 8; i++) {
        acc[i][0] = bias.x; acc[i][1] = bias.y; acc[i][2] = bias.z; acc[i][3] = bias.w;
    }
    for (int kh = 0; kh < 2; kh++) {
        __syncthreads();
        for (int i = tid; i < 48 * 96 / 4; i += 192)
            reinterpret_cast<float4*>(Wm)[i] =
                reinterpret_cast<const float4*>(W1b + kh * 48 * 96)[i];
        __syncthreads();
        #pragma unroll 4
        for (int k = 0; k < 48; k++) {
            int kg = kh * 48 + k;
            float4 w = *reinterpret_cast<float4*>(&Wm[k * 96 + c0]);
            #pragma unroll
            for (int i = 0; i < 8; i++) {
                float tv = zs[(r0 + i) * 97 + kg];
                acc[i][0] = fmaf(tv, w.x, acc[i][0]);
                acc[i][1] = fmaf(tv, w.y, acc[i][1]);
                acc[i][2] = fmaf(tv, w.z, acc[i][2]);
                acc[i][3] = fmaf(tv, w.w, acc[i][3]);
            }
        }
    }
    #pragma unroll
    for (int i = 0; i < 8; i++) {
        int row = row0 + r0 + i;
        if (row < N_NODES) {
            __half2 p0 = __floats2half2_rn(fmaxf(acc[i][0], 0.f), fmaxf(acc[i][1], 0.f));
            __half2 p1 = __floats2half2_rn(fmaxf(acc[i][2], 0.f), fmaxf(acc[i][3], 0.f));
            uint2 st;
            st.x = *reinterpret_cast<unsigned*>(&p0);
            st.y = *reinterpret_cast<unsigned*>(&p1);
            *reinterpret_cast<uint2*>(&h[(long long)row * D + c0]) = st;
        }
    }
}

// ---------------- MLP2 + head: register-tiled (exact R4) ----------------
#define M2 64
__global__ __launch_bounds__(128)
void k_mlp2(const float* __restrict__ z2,
            const float* __restrict__ W2a, const float* __restrict__ b2a,
            const float* __restrict__ W2b, const float* __restrict__ b2b,
            const float* __restrict__ Wh,  const float* __restrict__ bh,
            float* __restrict__ out) {
    __shared__ float zs[M2 * 97];
    __shared__ float W2a_s[D * H2];
    __shared__ float W2b_s[H2 * H2];
    __shared__ float Wh_s[H2 * OUTD];
    float* t_s = zs;
    float* b_s = zs + M2 * 33;

    const int tid = threadIdx.x;
    const int cg = tid % 8;
    const int rg = tid / 8;
    const int c0 = cg * 4;
    const int r0 = rg * 4;
    const int row0 = blockIdx.x * M2;

    for (int i = tid; i < D * H2 / 4;    i += 128)
        reinterpret_cast<float4*>(W2a_s)[i] = reinterpret_cast<const float4*>(W2a)[i];
    for (int i = tid; i < H2 * H2 / 4;   i += 128)
        reinterpret_cast<float4*>(W2b_s)[i] = reinterpret_cast<const float4*>(W2b)[i];
    for (int i = tid; i < H2 * OUTD; i += 128) Wh_s[i] = Wh[i];
    for (int i = tid; i < M2 * CH; i += 128) {
        int r = i / CH, kc = i % CH;
        float4 v = (row0 + r < N_NODES)
                 ? reinterpret_cast<const float4*>(z2)[(row0 + r) * CH + kc]
                 : make_float4(0.f, 0.f, 0.f, 0.f);
        zs[r * 97 + kc * 4 + 0] = v.x;
        zs[r * 97 + kc * 4 + 1] = v.y;
        zs[r * 97 + kc * 4 + 2] = v.z;
        zs[r * 97 + kc * 4 + 3] = v.w;
    }
    __syncthreads();

    float4 bias = *reinterpret_cast<const float4*>(&b2a[c0]);
    float acc[4][4];
    #pragma unroll
    for (int i = 0; i < 4; i++) {
        acc[i][0] = bias.x; acc[i][1] = bias.y; acc[i][2] = bias.z; acc[i][3] = bias.w;
    }
    #pragma unroll 4
    for (int k = 0; k < D; k++) {
        float4 w = *reinterpret_cast<float4*>(&W2a_s[k * H2 + c0]);
        #pragma unroll
        for (int i = 0; i < 4; i++) {
            float zv = zs[(r0 + i) * 97 + k];
            acc[i][0] = fmaf(zv, w.x, acc[i][0]);
            acc[i][1] = fmaf(zv, w.y, acc[i][1]);
            acc[i][2] = fmaf(zv, w.z, acc[i][2]);
            acc[i][3] = fmaf(zv, w.w, acc[i][3]);
        }
    }
    __syncthreads();
    #pragma unroll
    for (int i = 0; i < 4; i++) {
        t_s[(r0 + i) * 33 + c0 + 0] = fmaxf(acc[i][0], 0.f);
        t_s[(r0 + i) * 33 + c0 + 1] = fmaxf(acc[i][1], 0.f);
        t_s[(r0 + i) * 33 + c0 + 2] = fmaxf(acc[i][2], 0.f);
        t_s[(r0 + i) * 33 + c0 + 3] = fmaxf(acc[i][3], 0.f);
    }
    __syncthreads();

    bias = *reinterpret_cast<const float4*>(&b2b[c0]);
    #pragma unroll
    for (int i = 0; i < 4; i++) {
        acc[i][0] = bias.x; acc[i][1] = bias.y; acc[i][2] = bias.z; acc[i][3] = bias.w;
    }
    #pragma unroll 4
    for (int k = 0; k < H2; k++) {
        float4 w = *reinterpret_cast<float4*>(&W2b_s[k * H2 + c0]);
        #pragma unroll
        for (int i = 0; i < 4; i++) {
            float tv = t_s[(r0 + i) * 33 + k];
            acc[i][0] = fmaf(tv, w.x, acc[i][0]);
            acc[i][1] = fmaf(tv, w.y, acc[i][1]);
            acc[i][2] = fmaf(tv, w.z, acc[i][2]);
            acc[i][3] = fmaf(tv, w.w, acc[i][3]);
        }
    }
    __syncthreads();
    #pragma unroll
    for (int i = 0; i < 4; i++) {
        b_s[(r0 + i) * 33 + c0 + 0] = fmaxf(acc[i][0], 0.f);
        b_s[(r0 + i) * 33 + c0 + 1] = fmaxf(acc[i][1], 0.f);
        b_s[(r0 + i) * 33 + c0 + 2] = fmaxf(acc[i][2], 0.f);
        b_s[(r0 + i) * 33 + c0 + 3] = fmaxf(acc[i][3], 0.f);
    }
    __syncthreads();

    if (tid < M2) {
        int row = row0 + tid;
        if (row < N_NODES) {
            float o0 = bh[0], o1 = bh[1], o2 = bh[2], o3 = bh[3];
            #pragma unroll
            for (int k = 0; k < H2; k++) {
                float bv = b_s[tid * 33 + k];
                o0 = fmaf(bv, Wh_s[k * OUTD + 0], o0);
                o1 = fmaf(bv, Wh_s[k * OUTD + 1], o1);
                o2 = fmaf(bv, Wh_s[k * OUTD + 2], o2);
                o3 = fmaf(bv, Wh_s[k * OUTD + 3], o3);
            }
            float4 o = make_float4(o0, o1, o2, o3);
            *reinterpret_cast<float4*>(&out[(long long)row * OUTD]) = o;
        }
    }
}

extern "C" void kernel_launch(void* const* d_in, const int* in_sizes, int n_in,
                              void* d_out, int out_size) {
    const float* x    = (const float*)d_in[0];
    const int*   ei   = (const int*)  d_in[1];
    const float* eps1 = (const float*)d_in[2];
    const float* eps2 = (const float*)d_in[3];
    const float* W1a  = (const float*)d_in[4];
    const float* b1a  = (const float*)d_in[5];
    const float* W1b  = (const float*)d_in[6];
    const float* b1b  = (const float*)d_in[7];
    const float* W2a  = (const float*)d_in[8];
    const float* b2a  = (const float*)d_in[9];
    const float* W2b  = (const float*)d_in[10];
    const float* b2b  = (const float*)d_in[11];
    const float* Wh   = (const float*)d_in[12];
    const float* bh   = (const float*)d_in[13];
    float* out = (float*)d_out;

    float *z1, *z2;
    __half *x16, *h16;
    int *deg, *rowptr, *cursor, *bsum, *ebuf;
    cudaGetSymbolAddress((void**)&z1, g_z1);
    cudaGetSymbolAddress((void**)&z2, g_z2);
    cudaGetSymbolAddress((void**)&x16, g_x16);
    cudaGetSymbolAddress((void**)&h16, g_h16);
    cudaGetSymbolAddress((void**)&deg, g_deg);
    cudaGetSymbolAddress((void**)&rowptr, g_rowptr);
    cudaGetSymbolAddress((void**)&cursor, g_cursor);
    cudaGetSymbolAddress((void**)&bsum, g_bsum);
    cudaGetSymbolAddress((void**)&ebuf, g_ebuf);

    const int eb = (N_EDGES + 255) / 256;
    const int n4 = N_NODES * D / 4;
    const int cvt_blocks  = (n4 + 255) / 256;
    const int gagg_blocks = (N_NODES * 32 + 255) / 256;
    const int mlp1_blocks = (N_NODES + M1 - 1) / M1;
    const int mlp2_blocks = (N_NODES + M2 - 1) / M2;

    // x -> fp16 (independent of CSR)
    k_cvt<<<cvt_blocks, 256>>>(x, x16, n4);

    // CSR build (once, shared by both layers)
    cudaMemsetAsync(deg, 0, N_NODES * sizeof(int));
    k_hist<<<eb, 256>>>(ei, deg);
    k_scan1<<<SCAN_NB, SCAN_B>>>(deg, rowptr, bsum);
    k_scan2<<<1, 64>>>(bsum);
    k_scan3<<<SCAN_NB, SCAN_B>>>(rowptr, bsum, cursor);
    k_fill<<<eb, 256>>>(ei, cursor, ebuf);

    // Layer 1 (gather fp16, accumulate fp32)
    k_gagg_h<<<gagg_blocks, 256>>>(x16, eps1, rowptr, ebuf, z1);
    k_mlp1<<<mlp1_blocks, 192>>>(z1, W1a, b1a, W1b, b1b, h16);

    // Layer 2 (gather fp16 h, accumulate fp32)
    k_gagg_h<<<gagg_blocks, 256>>>(h16, eps2, rowptr, ebuf, z2);
    k_mlp2<<<mlp2_blocks, 128>>>(z2, W2a, b2a, W2b, b2b, Wh, bh, out);
}

// round 11
// speedup vs baseline: 1.3799x; 1.0002x over previous
#include <cuda_runtime.h>
#include <cuda_fp16.h>

#define N_NODES 50000
#define N_EDGES 800000
#define D       96
#define H2      32
#define OUTD    4
#define CH      (D/4)        // 24 float4 chunks per fp32 row
#define CH16    (D/8)        // 12 uint4 chunks per fp16 row
#define SCAN_B  1024
#define SCAN_NB ((N_NODES + SCAN_B - 1) / SCAN_B)   // 49

// Scratch (no allocations allowed)
__device__ float  g_z1[N_NODES * D];
__device__ float  g_z2[N_NODES * D];
__device__ __half g_x16[N_NODES * D];
__device__ __half g_h16[N_NODES * D];
// meta: [0, N_NODES) deg ; [N_NODES, +64) bsum ; [N_NODES+64, +128) flags
__device__ int    g_meta[N_NODES + 128];
__device__ int    g_rowptr[N_NODES + 1];
__device__ int    g_cursor[N_NODES];
__device__ int    g_ebuf[N_EDGES];

// ---------------- CSR build ----------------

__global__ void k_hist(const int* __restrict__ ei, int* __restrict__ deg) {
    int e = blockIdx.x * blockDim.x + threadIdx.x;
    if (e < N_EDGES) atomicAdd(&deg[ei[N_EDGES + e]], 1);
}

// single-kernel scan: 49 blocks x 1024, flag-based grid barrier.
// All 49 blocks are co-resident (49 << 148 SMs), so spinning is safe.
__global__ __launch_bounds__(SCAN_B)
void k_scan_one(int* __restrict__ meta, int* __restrict__ rowptr,
                int* __restrict__ cursor) {
    const int* deg  = meta;
    int* bsum = meta + N_NODES;
    volatile int* flag = meta + N_NODES + 64;
    __shared__ int s[SCAN_B];
    __shared__ int bs[64];
    __shared__ int boff_s;
    int t = threadIdx.x;
    int i = blockIdx.x * SCAN_B + t;
    int v = (i < N_NODES) ? deg[i] : 0;
    s[t] = v;
    __syncthreads();
    for (int off = 1; off < SCAN_B; off <<= 1) {
        int add = (t >= off) ? s[t - off] : 0;
        __syncthreads();
        s[t] += add;
        __syncthreads();
    }
    // publish block total, then flag (release)
    if (t == SCAN_B - 1) {
        bsum[blockIdx.x] = s[t];
        __threadfence();
        flag[blockIdx.x] = 1;
    }
    // wait for all block totals
    if (t < SCAN_NB) {
        while (flag[t] == 0) { }
    }
    __syncthreads();
    if (t < SCAN_NB) bs[t] = bsum[t];
    __syncthreads();
    if (t == 0) {
        int o = 0;
        for (int b = 0; b < blockIdx.x; b++) o += bs[b];
        boff_s = o;
    }
    __syncthreads();
    int r = s[t] - v + boff_s;    // global exclusive prefix
    if (i < N_NODES) {
        rowptr[i] = r;
        cursor[i] = r;
    }
    if (i == 0) rowptr[N_NODES] = N_EDGES;
}

__global__ void k_fill(const int* __restrict__ ei, int* __restrict__ cursor,
                       int* __restrict__ ebuf) {
    int e = blockIdx.x * blockDim.x + threadIdx.x;
    if (e < N_EDGES) {
        int dst = ei[N_EDGES + e];
        int pos = atomicAdd(&cursor[dst], 1);
        ebuf[pos] = ei[e];
    }
}

// ---------------- x -> fp16 convert ----------------
__global__ void k_cvt(const float* __restrict__ x, __half* __restrict__ x16, int n4) {
    int i = blockIdx.x * blockDim.x + threadIdx.x;
    if (i < n4) {
        float4 v = reinterpret_cast<const float4*>(x)[i];
        __half2 p0 = __floats2half2_rn(v.x, v.y);
        __half2 p1 = __floats2half2_rn(v.z, v.w);
        uint2 st;
        st.x = *reinterpret_cast<unsigned*>(&p0);
        st.y = *reinterpret_cast<unsigned*>(&p1);
        reinterpret_cast<uint2*>(x16)[i] = st;
    }
}

// ---------------- paired-edge fp16 gather (warp per node) ----------------
// Lanes 0-11 = group 0, lanes 12-23 = group 1; each group owns a full row
// (12 x uint4 = 96 halves) of a DIFFERENT edge -> 4 edges in flight with
// unroll 2 per group; serial chain per warp halves vs single-group walk.
__device__ __forceinline__ void acc_h8(float* acc, uint4 r) {
    __half2* h = reinterpret_cast<__half2*>(&r);
    #pragma unroll
    for (int q = 0; q < 4; q++) {
        float2 f2 = __half22float2(h[q]);
        acc[2 * q + 0] += f2.x;
        acc[2 * q + 1] += f2.y;
    }
}

__global__ __launch_bounds__(256)
void k_gagg_h(const __half* __restrict__ feat, const float* __restrict__ eps,
              const int* __restrict__ rowptr, const int* __restrict__ ebuf,
              float* __restrict__ z) {
    int warp = (blockIdx.x * blockDim.x + threadIdx.x) >> 5;
    int lane = threadIdx.x & 31;
    if (warp >= N_NODES) return;
    int beg = rowptr[warp];
    int end = rowptr[warp + 1];
    const uint4* f = reinterpret_cast<const uint4*>(feat);   // CH16 per row
    const bool act = lane < 24;
    const int  g   = (lane >= 12) ? 1 : 0;
    const int  gl  = lane - g * 12;                           // 0..11 (junk for lane>=24)

    float acc[8] = {0.f, 0.f, 0.f, 0.f, 0.f, 0.f, 0.f, 0.f};

    // self term (group 0 only; group 1's partial merges in at the end)
    if (lane < 12) {
        float s = 1.0f + *eps;
        uint4 r = f[warp * CH16 + lane];
        __half2* h = reinterpret_cast<__half2*>(&r);
        #pragma unroll
        for (int q = 0; q < 4; q++) {
            float2 f2 = __half22float2(h[q]);
            acc[2 * q + 0] = s * f2.x;
            acc[2 * q + 1] = s * f2.y;
        }
    }

    // 4 edges per iteration: group g handles e0+2g, e0+2g+1
    for (int e0 = beg; e0 < end; e0 += 4) {
        int eA = e0 + g * 2;
        if (act && eA < end) {
            int s0 = __ldg(&ebuf[eA]);
            int s1 = (eA + 1 < end) ? __ldg(&ebuf[eA + 1]) : -1;
            uint4 r0 = f[s0 * CH16 + gl];
            acc_h8(acc, r0);
            if (s1 >= 0) {
                uint4 r1 = f[s1 * CH16 + gl];
                acc_h8(acc, r1);
            }
        }
    }

    // merge group 1 into group 0
    #pragma unroll
    for (int q = 0; q < 8; q++)
        acc[q] += __shfl_down_sync(0xffffffffu, acc[q], 12);

    if (lane < 12) {
        float4* zp = reinterpret_cast<float4*>(z) + warp * CH + lane * 2;
        zp[0] = make_float4(acc[0], acc[1], acc[2], acc[3]);
        zp[1] = make_float4(acc[4], acc[5], acc[6], acc[7]);
    }
}

// ---------------- MLP1: register-tiled (R4-proven), h written as fp16 --------
#define M1   64
__global__ __launch_bounds__(192)
void k_mlp1(const float* __restrict__ z,
            const float* __restrict__ W1a, const float* __restrict__ b1a,
            const float* __restrict__ W1b, const float* __restrict__ b1b,
            __half* __restrict__ h) {
    __shared__ float zs[M1 * 97];
    __shared__ float Wm[48 * 96];
    const int tid = threadIdx.x;
    const int cg = tid % 24;
    const int rg = tid / 24;
    const int c0 = cg * 4;
    const int r0 = rg * 8;
    const int row0 = blockIdx.x * M1;

    for (int i = tid; i < M1 * CH; i += 192) {
        int r = i / CH, kc = i % CH;
        float4 v = (row0 + r < N_NODES)
                 ? reinterpret_cast<const float4*>(z)[(row0 + r) * CH + kc]
                 : make_float4(0.f, 0.f, 0.f, 0.f);
        zs[r * 97 + kc * 4 + 0] = v.x;
        zs[r * 97 + kc * 4 + 1] = v.y;
        zs[r * 97 + kc * 4 + 2] = v.z;
        zs[r * 97 + kc * 4 + 3] = v.w;
    }

    float4 bias = *reinterpret_cast<const float4*>(&b1a[c0]);
    float acc[8][4];
    #pragma unroll
    for (int i = 0; i < 8; i++) {
        acc[i][0] = bias.x; acc[i][1] = bias.y; acc[i][2] = bias.z; acc[i][3] = bias.w;
    }

    for (int kh = 0; kh < 2; kh++) {
        __syncthreads();
        for (int i = tid; i < 48 * 96 / 4; i += 192)
            reinterpret_cast<float4*>(Wm)[i] =
                reinterpret_cast<const float4*>(W1a + kh * 48 * 96)[i];
        __syncthreads();
        #pragma unroll 4
        for (int k = 0; k < 48; k++) {
            int kg = kh * 48 + k;
            float4 w = *reinterpret_cast<float4*>(&Wm[k * 96 + c0]);
            #pragma unroll
            for (int i = 0; i < 8; i++) {
                float zv = zs[(r0 + i) * 97 + kg];
                acc[i][0] = fmaf(zv, w.x, acc[i][0]);
                acc[i][1] = fmaf(zv, w.y, acc[i][1]);
                acc[i][2] = fmaf(zv, w.z, acc[i][2]);
                acc[i][3] = fmaf(zv, w.w, acc[i][3]);
            }
        }
    }
    __syncthreads();
    #pragma unroll
    for (int i = 0; i < 8; i++) {
        zs[(r0 + i) * 97 + c0 + 0] = fmaxf(acc[i][0], 0.f);
        zs[(r0 + i) * 97 + c0 + 1] = fmaxf(acc[i][1], 0.f);
        zs[(r0 + i) * 97 + c0 + 2] = fmaxf(acc[i][2], 0.f);
        zs[(r0 + i) * 97 + c0 + 3] = fmaxf(acc[i][3], 0.f);
    }

    bias = *reinterpret_cast<const float4*>(&b1b[c0]);
    #pragma unroll
    for (int i = 0; i < 8; i++) {
        acc[i][0] = bias.x; acc[i][1] = bias.y; acc[i][2] = bias.z; acc[i][3] = bias.w;
    }
    for (int kh = 0; kh < 2; kh++) {
        __syncthreads();
        for (int i = tid; i < 48 * 96 / 4; i += 192)
            reinterpret_cast<float4*>(Wm)[i] =
                reinterpret_cast<const float4*>(W1b + kh * 48 * 96)[i];
        __syncthreads();
        #pragma unroll 4
        for (int k = 0; k < 48; k++) {
            int kg = kh * 48 + k;
            float4 w = *reinterpret_cast<float4*>(&Wm[k * 96 + c0]);
            #pragma unroll
            for (int i = 0; i < 8; i++) {
                float tv = zs[(r0 + i) * 97 + kg];
                acc[i][0] = fmaf(tv, w.x, acc[i][0]);
                acc[i][1] = fmaf(tv, w.y, acc[i][1]);
                acc[i][2] = fmaf(tv, w.z, acc[i][2]);
                acc[i][3] = fmaf(tv, w.w, acc[i][3]);
            }
        }
    }
    #pragma unroll
    for (int i = 0; i < 8; i++) {
        int row = row0 + r0 + i;
        if (row < N_NODES) {
            __half2 p0 = __floats2half2_rn(fmaxf(acc[i][0], 0.f), fmaxf(acc[i][1], 0.f));
            __half2 p1 = __floats2half2_rn(fmaxf(acc[i][2], 0.f), fmaxf(acc[i][3], 0.f));
            uint2 st;
            st.x = *reinterpret_cast<unsigned*>(&p0);
            st.y = *reinterpret_cast<unsigned*>(&p1);
            *reinterpret_cast<uint2*>(&h[(long long)row * D + c0]) = st;
        }
    }
}

// ---------------- MLP2 + head: register-tiled (exact R4) ----------------
#define M2 64
__global__ __launch_bounds__(128)
void k_mlp2(const float* __restrict__ z2,
            const float* __restrict__ W2a, const float* __restrict__ b2a,
            const float* __restrict__ W2b, const float* __restrict__ b2b,
            const float* __restrict__ Wh,  const float* __restrict__ bh,
            float* __restrict__ out) {
    __shared__ float zs[M2 * 97];
    __shared__ float W2a_s[D * H2];
    __shared__ float W2b_s[H2 * H2];
    __shared__ float Wh_s[H2 * OUTD];
    float* t_s = zs;
    float* b_s = zs + M2 * 33;

    const int tid = threadIdx.x;
    const int cg = tid % 8;
    const int rg = tid / 8;
    const int c0 = cg * 4;
    const int r0 = rg * 4;
    const int row0 = blockIdx.x * M2;

    for (int i = tid; i < D * H2 / 4;    i += 128)
        reinterpret_cast<float4*>(W2a_s)[i] = reinterpret_cast<const float4*>(W2a)[i];
    for (int i = tid; i < H2 * H2 / 4;   i += 128)
        reinterpret_cast<float4*>(W2b_s)[i] = reinterpret_cast<const float4*>(W2b)[i];
    for (int i = tid; i < H2 * OUTD; i += 128) Wh_s[i] = Wh[i];
    for (int i = tid; i < M2 * CH; i += 128) {
        int r = i / CH, kc = i % CH;
        float4 v = (row0 + r < N_NODES)
                 ? reinterpret_cast<const float4*>(z2)[(row0 + r) * CH + kc]
                 : make_float4(0.f, 0.f, 0.f, 0.f);
        zs[r * 97 + kc * 4 + 0] = v.x;
        zs[r * 97 + kc * 4 + 1] = v.y;
        zs[r * 97 + kc * 4 + 2] = v.z;
        zs[r * 97 + kc * 4 + 3] = v.w;
    }
    __syncthreads();

    float4 bias = *reinterpret_cast<const float4*>(&b2a[c0]);
    float acc[4][4];
    #pragma unroll
    for (int i = 0; i < 4; i++) {
        acc[i][0] = bias.x; acc[i][1] = bias.y; acc[i][2] = bias.z; acc[i][3] = bias.w;
    }
    #pragma unroll 4
    for (int k = 0; k < D; k++) {
        float4 w = *reinterpret_cast<float4*>(&W2a_s[k * H2 + c0]);
        #pragma unroll
        for (int i = 0; i < 4; i++) {
            float zv = zs[(r0 + i) * 97 + k];
            acc[i][0] = fmaf(zv, w.x, acc[i][0]);
            acc[i][1] = fmaf(zv, w.y, acc[i][1]);
            acc[i][2] = fmaf(zv, w.z, acc[i][2]);
            acc[i][3] = fmaf(zv, w.w, acc[i][3]);
        }
    }
    __syncthreads();
    #pragma unroll
    for (int i = 0; i < 4; i++) {
        t_s[(r0 + i) * 33 + c0 + 0] = fmaxf(acc[i][0], 0.f);
        t_s[(r0 + i) * 33 + c0 + 1] = fmaxf(acc[i][1], 0.f);
        t_s[(r0 + i) * 33 + c0 + 2] = fmaxf(acc[i][2], 0.f);
        t_s[(r0 + i) * 33 + c0 + 3] = fmaxf(acc[i][3], 0.f);
    }
    __syncthreads();

    bias = *reinterpret_cast<const float4*>(&b2b[c0]);
    #pragma unroll
    for (int i = 0; i < 4; i++) {
        acc[i][0] = bias.x; acc[i][1] = bias.y; acc[i][2] = bias.z; acc[i][3] = bias.w;
    }
    #pragma unroll 4
    for (int k = 0; k < H2; k++) {
        float4 w = *reinterpret_cast<float4*>(&W2b_s[k * H2 + c0]);
        #pragma unroll
        for (int i = 0; i < 4; i++) {
            float tv = t_s[(r0 + i) * 33 + k];
            acc[i][0] = fmaf(tv, w.x, acc[i][0]);
            acc[i][1] = fmaf(tv, w.y, acc[i][1]);
            acc[i][2] = fmaf(tv, w.z, acc[i][2]);
            acc[i][3] = fmaf(tv, w.w, acc[i][3]);
        }
    }
    __syncthreads();
    #pragma unroll
    for (int i = 0; i < 4; i++) {
        b_s[(r0 + i) * 33 + c0 + 0] = fmaxf(acc[i][0], 0.f);
        b_s[(r0 + i) * 33 + c0 + 1] = fmaxf(acc[i][1], 0.f);
        b_s[(r0 + i) * 33 + c0 + 2] = fmaxf(acc[i][2], 0.f);
        b_s[(r0 + i) * 33 + c0 + 3] = fmaxf(acc[i][3], 0.f);
    }
    __syncthreads();

    if (tid < M2) {
        int row = row0 + tid;
        if (row < N_NODES) {
            float o0 = bh[0], o1 = bh[1], o2 = bh[2], o3 = bh[3];
            #pragma unroll
            for (int k = 0; k < H2; k++) {
                float bv = b_s[tid * 33 + k];
                o0 = fmaf(bv, Wh_s[k * OUTD + 0], o0);
                o1 = fmaf(bv, Wh_s[k * OUTD + 1], o1);
                o2 = fmaf(bv, Wh_s[k * OUTD + 2], o2);
                o3 = fmaf(bv, Wh_s[k * OUTD + 3], o3);
            }
            float4 o = make_float4(o0, o1, o2, o3);
            *reinterpret_cast<float4*>(&out[(long long)row * OUTD]) = o;
        }
    }
}

extern "C" void kernel_launch(void* const* d_in, const int* in_sizes, int n_in,
                              void* d_out, int out_size) {
    const float* x    = (const float*)d_in[0];
    const int*   ei   = (const int*)  d_in[1];
    const float* eps1 = (const float*)d_in[2];
    const float* eps2 = (const float*)d_in[3];
    const float* W1a  = (const float*)d_in[4];
    const float* b1a  = (const float*)d_in[5];
    const float* W1b  = (const float*)d_in[6];
    const float* b1b  = (const float*)d_in[7];
    const float* W2a  = (const float*)d_in[8];
    const float* b2a  = (const float*)d_in[9];
    const float* W2b  = (const float*)d_in[10];
    const float* b2b  = (const float*)d_in[11];
    const float* Wh   = (const float*)d_in[12];
    const float* bh   = (const float*)d_in[13];
    float* out = (float*)d_out;

    float *z1, *z2;
    __half *x16, *h16;
    int *meta, *rowptr, *cursor, *ebuf;
    cudaGetSymbolAddress((void**)&z1, g_z1);
    cudaGetSymbolAddress((void**)&z2, g_z2);
    cudaGetSymbolAddress((void**)&x16, g_x16);
    cudaGetSymbolAddress((void**)&h16, g_h16);
    cudaGetSymbolAddress((void**)&meta, g_meta);
    cudaGetSymbolAddress((void**)&rowptr, g_rowptr);
    cudaGetSymbolAddress((void**)&cursor, g_cursor);
    cudaGetSymbolAddress((void**)&ebuf, g_ebuf);

    const int eb = (N_EDGES + 255) / 256;
    const int n4 = N_NODES * D / 4;
    const int cvt_blocks  = (n4 + 255) / 256;
    const int gagg_blocks = (N_NODES * 32 + 255) / 256;
    const int mlp1_blocks = (N_NODES + M1 - 1) / M1;
    const int mlp2_blocks = (N_NODES + M2 - 1) / M2;

    // x -> fp16 (independent of CSR)
    k_cvt<<<cvt_blocks, 256>>>(x, x16, n4);

    // CSR build: memset (deg + bsum + flags in one region), hist, 1-kernel scan, fill
    cudaMemsetAsync(meta, 0, (N_NODES + 128) * sizeof(int));
    k_hist<<<eb, 256>>>(ei, meta);
    k_scan_one<<<SCAN_NB, SCAN_B>>>(meta, rowptr, cursor);
    k_fill<<<eb, 256>>>(ei, cursor, ebuf);

    // Layer 1 (gather fp16 paired-edge, accumulate fp32)
    k_gagg_h<<<gagg_blocks, 256>>>(x16, eps1, rowptr, ebuf, z1);
    k_mlp1<<<mlp1_blocks, 192>>>(z1, W1a, b1a, W1b, b1b, h16);

    // Layer 2
    k_gagg_h<<<gagg_blocks, 256>>>(h16, eps2, rowptr, ebuf, z2);
    k_mlp2<<<mlp2_blocks, 128>>>(z2, W2a, b2a, W2b, b2b, Wh, bh, out);
}

// round 15
// speedup vs baseline: 1.5830x; 1.1471x over previous
#include <cuda_runtime.h>
#include <cuda_fp16.h>
#include <mma.h>
using namespace nvcuda;

#define N_NODES 50000
#define N_EDGES 800000
#define D       96
#define H2      32
#define OUTD    4
#define CH      (D/4)        // 24 float4 chunks per fp32 row
#define CH16    (D/8)        // 12 uint4 chunks per fp16 row
#define SCAN_B  1024
#define SCAN_NB ((N_NODES + SCAN_B - 1) / SCAN_B)   // 49

// Scratch (no allocations allowed)
__device__ __half g_x16[N_NODES * D];
__device__ __half g_z116[N_NODES * D];
__device__ __half g_h16[N_NODES * D];
__device__ float  g_z2[N_NODES * D];
__device__ __half g_w1a16[D * D];
__device__ __half g_w1b16[D * D];
// meta: [0, N_NODES) deg ; [N_NODES, +64) bsum ; [N_NODES+64, +128) flags
__device__ int    g_meta[N_NODES + 128];
__device__ int    g_rowptr[N_NODES + 1];
__device__ int    g_rank[N_EDGES];
__device__ int    g_ebuf[N_EDGES];

// ---------------- converts ----------------
__global__ void k_cvt(const float* __restrict__ x, __half* __restrict__ x16, int n4) {
    int i = blockIdx.x * blockDim.x + threadIdx.x;
    if (i < n4) {
        float4 v = reinterpret_cast<const float4*>(x)[i];
        __half2 p0 = __floats2half2_rn(v.x, v.y);
        __half2 p1 = __floats2half2_rn(v.z, v.w);
        uint2 st;
        st.x = *reinterpret_cast<unsigned*>(&p0);
        st.y = *reinterpret_cast<unsigned*>(&p1);
        reinterpret_cast<uint2*>(x16)[i] = st;
    }
}

__global__ void k_cvtw(const float* __restrict__ Wa, const float* __restrict__ Wb,
                       __half* __restrict__ wa, __half* __restrict__ wb) {
    int i = blockIdx.x * blockDim.x + threadIdx.x;
    if (i < D * D) {
        wa[i] = __float2half_rn(Wa[i]);
        wb[i] = __float2half_rn(Wb[i]);
    }
}

// ---------------- CSR build ----------------
__global__ void k_hist(const int* __restrict__ ei, int* __restrict__ deg,
                       int* __restrict__ rank) {
    int e = blockIdx.x * blockDim.x + threadIdx.x;
    if (e < N_EDGES) rank[e] = atomicAdd(&deg[ei[N_EDGES + e]], 1);
}

__global__ __launch_bounds__(SCAN_B)
void k_scan_one(int* __restrict__ meta, int* __restrict__ rowptr) {
    const int* deg  = meta;
    int* bsum = meta + N_NODES;
    volatile int* flag = meta + N_NODES + 64;
    __shared__ int s[SCAN_B];
    __shared__ int bs[64];
    __shared__ int boff_s;
    int t = threadIdx.x;
    int i = blockIdx.x * SCAN_B + t;
    int v = (i < N_NODES) ? deg[i] : 0;
    s[t] = v;
    __syncthreads();
    for (int off = 1; off < SCAN_B; off <<= 1) {
        int add = (t >= off) ? s[t - off] : 0;
        __syncthreads();
        s[t] += add;
        __syncthreads();
    }
    if (t == SCAN_B - 1) {
        bsum[blockIdx.x] = s[t];
        __threadfence();
        flag[blockIdx.x] = 1;
    }
    if (t < SCAN_NB) {
        while (flag[t] == 0) { }
    }
    __syncthreads();
    if (t < SCAN_NB) bs[t] = bsum[t];
    __syncthreads();
    if (t == 0) {
        int o = 0;
        for (int b = 0; b < blockIdx.x; b++) o += bs[b];
        boff_s = o;
    }
    __syncthreads();
    if (i < N_NODES) rowptr[i] = s[t] - v + boff_s;
    if (i == 0) rowptr[N_NODES] = N_EDGES;
}

__global__ void k_fill(const int* __restrict__ ei, const int* __restrict__ rank,
                       const int* __restrict__ rowptr, int* __restrict__ ebuf) {
    int e = blockIdx.x * blockDim.x + threadIdx.x;
    if (e < N_EDGES) {
        int dst = ei[N_EDGES + e];
        ebuf[rowptr[dst] + rank[e]] = ei[e];
    }
}

// ---------------- paired-edge fp16 gather ----------------
__device__ __forceinline__ void acc_h8(float* acc, uint4 r) {
    __half2* h = reinterpret_cast<__half2*>(&r);
    #pragma unroll
    for (int q = 0; q < 4; q++) {
        float2 f2 = __half22float2(h[q]);
        acc[2 * q + 0] += f2.x;
        acc[2 * q + 1] += f2.y;
    }
}

// Layer-1: fp16 in, fp16 out
__global__ __launch_bounds__(256)
void k_gagg16(const __half* __restrict__ feat, const float* __restrict__ eps,
              const int* __restrict__ rowptr, const int* __restrict__ ebuf,
              __half* __restrict__ z16) {
    int warp = (blockIdx.x * blockDim.x + threadIdx.x) >> 5;
    int lane = threadIdx.x & 31;
    if (warp >= N_NODES) return;
    int beg = rowptr[warp];
    int end = rowptr[warp + 1];
    const uint4* f = reinterpret_cast<const uint4*>(feat);
    const bool act = lane < 24;
    const int  g   = (lane >= 12) ? 1 : 0;
    const int  gl  = lane - g * 12;

    float acc[8] = {0.f, 0.f, 0.f, 0.f, 0.f, 0.f, 0.f, 0.f};
    if (lane < 12) {
        float s = 1.0f + *eps;
        uint4 r = f[warp * CH16 + lane];
        __half2* h = reinterpret_cast<__half2*>(&r);
        #pragma unroll
        for (int q = 0; q < 4; q++) {
            float2 f2 = __half22float2(h[q]);
            acc[2 * q + 0] = s * f2.x;
            acc[2 * q + 1] = s * f2.y;
        }
    }
    for (int e0 = beg; e0 < end; e0 += 4) {
        int eA = e0 + g * 2;
        if (act && eA < end) {
            int s0 = __ldg(&ebuf[eA]);
            int s1 = (eA + 1 < end) ? __ldg(&ebuf[eA + 1]) : -1;
            uint4 r0 = f[s0 * CH16 + gl];
            acc_h8(acc, r0);
            if (s1 >= 0) {
                uint4 r1 = f[s1 * CH16 + gl];
                acc_h8(acc, r1);
            }
        }
    }
    #pragma unroll
    for (int q = 0; q < 8; q++)
        acc[q] += __shfl_down_sync(0xffffffffu, acc[q], 12);
    if (lane < 12) {
        __half2 p0 = __floats2half2_rn(acc[0], acc[1]);
        __half2 p1 = __floats2half2_rn(acc[2], acc[3]);
        __half2 p2 = __floats2half2_rn(acc[4], acc[5]);
        __half2 p3 = __floats2half2_rn(acc[6], acc[7]);
        uint4 st;
        st.x = *reinterpret_cast<unsigned*>(&p0);
        st.y = *reinterpret_cast<unsigned*>(&p1);
        st.z = *reinterpret_cast<unsigned*>(&p2);
        st.w = *reinterpret_cast<unsigned*>(&p3);
        reinterpret_cast<uint4*>(z16)[warp * CH16 + lane] = st;
    }
}

// Layer-2: fp16 in, fp32 out
__global__ __launch_bounds__(256)
void k_gagg32f(const __half* __restrict__ feat, const float* __restrict__ eps,
               const int* __restrict__ rowptr, const int* __restrict__ ebuf,
               float* __restrict__ z) {
    int warp = (blockIdx.x * blockDim.x + threadIdx.x) >> 5;
    int lane = threadIdx.x & 31;
    if (warp >= N_NODES) return;
    int beg = rowptr[warp];
    int end = rowptr[warp + 1];
    const uint4* f = reinterpret_cast<const uint4*>(feat);
    const bool act = lane < 24;
    const int  g   = (lane >= 12) ? 1 : 0;
    const int  gl  = lane - g * 12;

    float acc[8] = {0.f, 0.f, 0.f, 0.f, 0.f, 0.f, 0.f, 0.f};
    if (lane < 12) {
        float s = 1.0f + *eps;
        uint4 r = f[warp * CH16 + lane];
        __half2* h = reinterpret_cast<__half2*>(&r);
        #pragma unroll
        for (int q = 0; q < 4; q++) {
            float2 f2 = __half22float2(h[q]);
            acc[2 * q + 0] = s * f2.x;
            acc[2 * q + 1] = s * f2.y;
        }
    }
    for (int e0 = beg; e0 < end; e0 += 4) {
        int eA = e0 + g * 2;
        if (act && eA < end) {
            int s0 = __ldg(&ebuf[eA]);
            int s1 = (eA + 1 < end) ? __ldg(&ebuf[eA + 1]) : -1;
            uint4 r0 = f[s0 * CH16 + gl];
            acc_h8(acc, r0);
            if (s1 >= 0) {
                uint4 r1 = f[s1 * CH16 + gl];
                acc_h8(acc, r1);
            }
        }
    }
    #pragma unroll
    for (int q = 0; q < 8; q++)
        acc[q] += __shfl_down_sync(0xffffffffu, acc[q], 12);
    if (lane < 12) {
        float4* zp = reinterpret_cast<float4*>(z) + warp * CH + lane * 2;
        zp[0] = make_float4(acc[0], acc[1], acc[2], acc[3]);
        zp[1] = make_float4(acc[4], acc[5], acc[6], acc[7]);
    }
}

// ---------------- MLP1 via WMMA fp16 (fp32 accumulate) ----------------
// FIXED smem layout (Bs is 96x96 = 18432 B; no Ts/Bs overlap):
//   As [0, 12288)      64x96 fp16   (z tile)
//   Bs [12288, 30720)  96x96 fp16   (weight)
//   Ts [30720, 43008)  64x96 fp16   (t activations)
//   Ct [0, 24576)      64x96 fp32   (aliases As + Bs head; only dead data clobbered)
#define M1 64
__global__ __launch_bounds__(256)
void k_mlp1_w(const __half* __restrict__ z16,
              const __half* __restrict__ wa, const float* __restrict__ b1a,
              const __half* __restrict__ wb, const float* __restrict__ b1b,
              __half* __restrict__ h) {
    __shared__ __align__(16) char pool[43008];
    __half* As = reinterpret_cast<__half*>(pool);
    __half* Bs = reinterpret_cast<__half*>(pool + 12288);
    __half* Ts = reinterpret_cast<__half*>(pool + 30720);
    float*  Ct = reinterpret_cast<float*>(pool);
    const int tid = threadIdx.x;
    const int wid = tid >> 5;
    const int row0 = blockIdx.x * M1;
    const int strip = wid >> 1;           // 0..3
    const int cbase = (wid & 1) * 48;     // 0 or 48

    // stage A (z tile, zero-pad OOB rows) and B (W1a)
    {
        uint4* Au = reinterpret_cast<uint4*>(As);
        const uint4* Zu = reinterpret_cast<const uint4*>(z16);
        for (int i = tid; i < M1 * CH16; i += 256) {
            int r = i / CH16;
            Au[i] = (row0 + r < N_NODES) ? Zu[(row0 + r) * CH16 + (i % CH16)]
                                         : make_uint4(0u, 0u, 0u, 0u);
        }
        uint4* Bu = reinterpret_cast<uint4*>(Bs);
        const uint4* Wu = reinterpret_cast<const uint4*>(wa);
        for (int i = tid; i < D * D / 8; i += 256) Bu[i] = Wu[i];
    }
    __syncthreads();

    wmma::fragment<wmma::accumulator, 16, 16, 16, float> acc[3];
    #pragma unroll
    for (int j = 0; j < 3; j++) wmma::fill_fragment(acc[j], 0.0f);
    #pragma unroll
    for (int k = 0; k < 6; k++) {
        wmma::fragment<wmma::matrix_a, 16, 16, 16, __half, wmma::row_major> a;
        wmma::load_matrix_sync(a, As + strip * 16 * D + k * 16, D);
        #pragma unroll
        for (int j = 0; j < 3; j++) {
            wmma::fragment<wmma::matrix_b, 16, 16, 16, __half, wmma::row_major> b;
            wmma::load_matrix_sync(b, Bs + (k * 16) * D + cbase + j * 16, D);
            wmma::mma_sync(acc[j], a, b, acc[j]);
        }
    }
    __syncthreads();      // all As/Bs reads done
    #pragma unroll
    for (int j = 0; j < 3; j++)
        wmma::store_matrix_sync(Ct + strip * 16 * D + cbase + j * 16, acc[j], D,
                                wmma::mem_row_major);
    __syncthreads();

    // epilogue 1: t = fp16(relu(C + b1a)) -> Ts (no overlap with Ct)
    for (int i = tid; i < M1 * CH16; i += 256) {
        int r = i / CH16, c0 = (i % CH16) * 8;
        float4 v0 = *reinterpret_cast<float4*>(&Ct[r * D + c0]);
        float4 v1 = *reinterpret_cast<float4*>(&Ct[r * D + c0 + 4]);
        float4 ba0 = *reinterpret_cast<const float4*>(&b1a[c0]);
        float4 ba1 = *reinterpret_cast<const float4*>(&b1a[c0 + 4]);
        __half2 p0 = __floats2half2_rn(fmaxf(v0.x + ba0.x, 0.f), fmaxf(v0.y + ba0.y, 0.f));
        __half2 p1 = __floats2half2_rn(fmaxf(v0.z + ba0.z, 0.f), fmaxf(v0.w + ba0.w, 0.f));
        __half2 p2 = __floats2half2_rn(fmaxf(v1.x + ba1.x, 0.f), fmaxf(v1.y + ba1.y, 0.f));
        __half2 p3 = __floats2half2_rn(fmaxf(v1.z + ba1.z, 0.f), fmaxf(v1.w + ba1.w, 0.f));
        uint4 st;
        st.x = *reinterpret_cast<unsigned*>(&p0);
        st.y = *reinterpret_cast<unsigned*>(&p1);
        st.z = *reinterpret_cast<unsigned*>(&p2);
        st.w = *reinterpret_cast<unsigned*>(&p3);
        reinterpret_cast<uint4*>(Ts)[i] = st;
    }
    __syncthreads();

    // stage W1b -> Bs (overwrites Ct[3072..6144) — Ct fully consumed above)
    {
        uint4* Bu = reinterpret_cast<uint4*>(Bs);
        const uint4* Wu = reinterpret_cast<const uint4*>(wb);
        for (int i = tid; i < D * D / 8; i += 256) Bu[i] = Wu[i];
    }
    __syncthreads();

    #pragma unroll
    for (int j = 0; j < 3; j++) wmma::fill_fragment(acc[j], 0.0f);
    #pragma unroll
    for (int k = 0; k < 6; k++) {
        wmma::fragment<wmma::matrix_a, 16, 16, 16, __half, wmma::row_major> a;
        wmma::load_matrix_sync(a, Ts + strip * 16 * D + k * 16, D);
        #pragma unroll
        for (int j = 0; j < 3; j++) {
            wmma::fragment<wmma::matrix_b, 16, 16, 16, __half, wmma::row_major> b;
            wmma::load_matrix_sync(b, Bs + (k * 16) * D + cbase + j * 16, D);
            wmma::mma_sync(acc[j], a, b, acc[j]);
        }
    }
    __syncthreads();      // all Ts/Bs reads done
    #pragma unroll
    for (int j = 0; j < 3; j++)
        wmma::store_matrix_sync(Ct + strip * 16 * D + cbase + j * 16, acc[j], D,
                                wmma::mem_row_major);
    __syncthreads();

    // epilogue 2: h = fp16(relu(C + b1b)) -> gmem
    for (int i = tid; i < M1 * CH16; i += 256) {
        int r = i / CH16, c0 = (i % CH16) * 8;
        int row = row0 + r;
        if (row < N_NODES) {
            float4 v0 = *reinterpret_cast<float4*>(&Ct[r * D + c0]);
            float4 v1 = *reinterpret_cast<float4*>(&Ct[r * D + c0 + 4]);
            float4 bb0 = *reinterpret_cast<const float4*>(&b1b[c0]);
            float4 bb1 = *reinterpret_cast<const float4*>(&b1b[c0 + 4]);
            __half2 p0 = __floats2half2_rn(fmaxf(v0.x + bb0.x, 0.f), fmaxf(v0.y + bb0.y, 0.f));
            __half2 p1 = __floats2half2_rn(fmaxf(v0.z + bb0.z, 0.f), fmaxf(v0.w + bb0.w, 0.f));
            __half2 p2 = __floats2half2_rn(fmaxf(v1.x + bb1.x, 0.f), fmaxf(v1.y + bb1.y, 0.f));
            __half2 p3 = __floats2half2_rn(fmaxf(v1.z + bb1.z, 0.f), fmaxf(v1.w + bb1.w, 0.f));
            uint4 st;
            st.x = *reinterpret_cast<unsigned*>(&p0);
            st.y = *reinterpret_cast<unsigned*>(&p1);
            st.z = *reinterpret_cast<unsigned*>(&p2);
            st.w = *reinterpret_cast<unsigned*>(&p3);
            *reinterpret_cast<uint4*>(&h[(long long)row * D + c0]) = st;
        }
    }
}

// ---------------- MLP2 + head: register-tiled fp32 (proven) ----------------
#define M2 64
__global__ __launch_bounds__(128)
void k_mlp2(const float* __restrict__ z2,
            const float* __restrict__ W2a, const float* __restrict__ b2a,
            const float* __restrict__ W2b, const float* __restrict__ b2b,
            const float* __restrict__ Wh,  const float* __restrict__ bh,
            float* __restrict__ out) {
    __shared__ float zs[M2 * 97];
    __shared__ float W2a_s[D * H2];
    __shared__ float W2b_s[H2 * H2];
    __shared__ float Wh_s[H2 * OUTD];
    float* t_s = zs;
    float* b_s = zs + M2 * 33;

    const int tid = threadIdx.x;
    const int cg = tid % 8;
    const int rg = tid / 8;
    const int c0 = cg * 4;
    const int r0 = rg * 4;
    const int row0 = blockIdx.x * M2;

    for (int i = tid; i < D * H2 / 4;    i += 128)
        reinterpret_cast<float4*>(W2a_s)[i] = reinterpret_cast<const float4*>(W2a)[i];
    for (int i = tid; i < H2 * H2 / 4;   i += 128)
        reinterpret_cast<float4*>(W2b_s)[i] = reinterpret_cast<const float4*>(W2b)[i];
    for (int i = tid; i < H2 * OUTD; i += 128) Wh_s[i] = Wh[i];
    for (int i = tid; i < M2 * CH; i += 128) {
        int r = i / CH, kc = i % CH;
        float4 v = (row0 + r < N_NODES)
                 ? reinterpret_cast<const float4*>(z2)[(row0 + r) * CH + kc]
                 : make_float4(0.f, 0.f, 0.f, 0.f);
        zs[r * 97 + kc * 4 + 0] = v.x;
        zs[r * 97 + kc * 4 + 1] = v.y;
        zs[r * 97 + kc * 4 + 2] = v.z;
        zs[r * 97 + kc * 4 + 3] = v.w;
    }
    __syncthreads();

    float4 bias = *reinterpret_cast<const float4*>(&b2a[c0]);
    float acc[4][4];
    #pragma unroll
    for (int i = 0; i < 4; i++) {
        acc[i][0] = bias.x; acc[i][1] = bias.y; acc[i][2] = bias.z; acc[i][3] = bias.w;
    }
    #pragma unroll 4
    for (int k = 0; k < D; k++) {
        float4 w = *reinterpret_cast<float4*>(&W2a_s[k * H2 + c0]);
        #pragma unroll
        for (int i = 0; i < 4; i++) {
            float zv = zs[(r0 + i) * 97 + k];
            acc[i][0] = fmaf(zv, w.x, acc[i][0]);
            acc[i][1] = fmaf(zv, w.y, acc[i][1]);
            acc[i][2] = fmaf(zv, w.z, acc[i][2]);
            acc[i][3] = fmaf(zv, w.w, acc[i][3]);
        }
    }
    __syncthreads();
    #pragma unroll
    for (int i = 0; i < 4; i++) {
        t_s[(r0 + i) * 33 + c0 + 0] = fmaxf(acc[i][0], 0.f);
        t_s[(r0 + i) * 33 + c0 + 1] = fmaxf(acc[i][1], 0.f);
        t_s[(r0 + i) * 33 + c0 + 2] = fmaxf(acc[i][2], 0.f);
        t_s[(r0 + i) * 33 + c0 + 3] = fmaxf(acc[i][3], 0.f);
    }
    __syncthreads();

    bias = *reinterpret_cast<const float4*>(&b2b[c0]);
    #pragma unroll
    for (int i = 0; i < 4; i++) {
        acc[i][0] = bias.x; acc[i][1] = bias.y; acc[i][2] = bias.z; acc[i][3] = bias.w;
    }
    #pragma unroll 4
    for (int k = 0; k < H2; k++) {
        float4 w = *reinterpret_cast<float4*>(&W2b_s[k * H2 + c0]);
        #pragma unroll
        for (int i = 0; i < 4; i++) {
            float tv = t_s[(r0 + i) * 33 + k];
            acc[i][0] = fmaf(tv, w.x, acc[i][0]);
            acc[i][1] = fmaf(tv, w.y, acc[i][1]);
            acc[i][2] = fmaf(tv, w.z, acc[i][2]);
            acc[i][3] = fmaf(tv, w.w, acc[i][3]);
        }
    }
    __syncthreads();
    #pragma unroll
    for (int i = 0; i < 4; i++) {
        b_s[(r0 + i) * 33 + c0 + 0] = fmaxf(acc[i][0], 0.f);
        b_s[(r0 + i) * 33 + c0 + 1] = fmaxf(acc[i][1], 0.f);
        b_s[(r0 + i) * 33 + c0 + 2] = fmaxf(acc[i][2], 0.f);
        b_s[(r0 + i) * 33 + c0 + 3] = fmaxf(acc[i][3], 0.f);
    }
    __syncthreads();

    if (tid < M2) {
        int row = row0 + tid;
        if (row < N_NODES) {
            float o0 = bh[0], o1 = bh[1], o2 = bh[2], o3 = bh[3];
            #pragma unroll
            for (int k = 0; k < H2; k++) {
                float bv = b_s[tid * 33 + k];
                o0 = fmaf(bv, Wh_s[k * OUTD + 0], o0);
                o1 = fmaf(bv, Wh_s[k * OUTD + 1], o1);
                o2 = fmaf(bv, Wh_s[k * OUTD + 2], o2);
                o3 = fmaf(bv, Wh_s[k * OUTD + 3], o3);
            }
            float4 o = make_float4(o0, o1, o2, o3);
            *reinterpret_cast<float4*>(&out[(long long)row * OUTD]) = o;
        }
    }
}

extern "C" void kernel_launch(void* const* d_in, const int* in_sizes, int n_in,
                              void* d_out, int out_size) {
    const float* x    = (const float*)d_in[0];
    const int*   ei   = (const int*)  d_in[1];
    const float* eps1 = (const float*)d_in[2];
    const float* eps2 = (const float*)d_in[3];
    const float* W1a  = (const float*)d_in[4];
    const float* b1a  = (const float*)d_in[5];
    const float* W1b  = (const float*)d_in[6];
    const float* b1b  = (const float*)d_in[7];
    const float* W2a  = (const float*)d_in[8];
    const float* b2a  = (const float*)d_in[9];
    const float* W2b  = (const float*)d_in[10];
    const float* b2b  = (const float*)d_in[11];
    const float* Wh   = (const float*)d_in[12];
    const float* bh   = (const float*)d_in[13];
    float* out = (float*)d_out;

    __half *x16, *z116, *h16, *wa16, *wb16;
    float *z2;
    int *meta, *rowptr, *rank, *ebuf;
    cudaGetSymbolAddress((void**)&x16, g_x16);
    cudaGetSymbolAddress((void**)&z116, g_z116);
    cudaGetSymbolAddress((void**)&h16, g_h16);
    cudaGetSymbolAddress((void**)&wa16, g_w1a16);
    cudaGetSymbolAddress((void**)&wb16, g_w1b16);
    cudaGetSymbolAddress((void**)&z2, g_z2);
    cudaGetSymbolAddress((void**)&meta, g_meta);
    cudaGetSymbolAddress((void**)&rowptr, g_rowptr);
    cudaGetSymbolAddress((void**)&rank, g_rank);
    cudaGetSymbolAddress((void**)&ebuf, g_ebuf);

    const int eb = (N_EDGES + 255) / 256;
    const int n4 = N_NODES * D / 4;
    const int cvt_blocks  = (n4 + 255) / 256;
    const int cvtw_blocks = (D * D + 255) / 256;
    const int gagg_blocks = (N_NODES * 32 + 255) / 256;
    const int mlp1_blocks = (N_NODES + M1 - 1) / M1;
    const int mlp2_blocks = (N_NODES + M2 - 1) / M2;

    // converts (independent of CSR)
    k_cvt<<<cvt_blocks, 256>>>(x, x16, n4);
    k_cvtw<<<cvtw_blocks, 256>>>(W1a, W1b, wa16, wb16);

    // CSR build: memset, hist (captures per-edge rank), scan, atomic-free fill
    cudaMemsetAsync(meta, 0, (N_NODES + 128) * sizeof(int));
    k_hist<<<eb, 256>>>(ei, meta, rank);
    k_scan_one<<<SCAN_NB, SCAN_B>>>(meta, rowptr);
    k_fill<<<eb, 256>>>(ei, rank, rowptr, ebuf);

    // Layer 1: gather (fp16 out) -> WMMA MLP
    k_gagg16<<<gagg_blocks, 256>>>(x16, eps1, rowptr, ebuf, z116);
    k_mlp1_w<<<mlp1_blocks, 256>>>(z116, wa16, b1a, wb16, b1b, h16);

    // Layer 2: gather (fp32 out) -> fp32 MLP + head
    k_gagg32f<<<gagg_blocks, 256>>>(h16, eps2, rowptr, ebuf, z2);
    k_mlp2<<<mlp2_blocks, 128>>>(z2, W2a, b2a, W2b, b2b, Wh, bh, out);
}

// round 16
// speedup vs baseline: 1.7211x; 1.0873x over previous
#include <cuda_runtime.h>
#include <cuda_fp16.h>
#include <mma.h>
using namespace nvcuda;

#define N_NODES 50000
#define N_EDGES 800000
#define D       96
#define H2      32
#define OUTD    4
#define CH      (D/4)
#define CH16    (D/8)        // 12 uint4 chunks per fp16 row
#define SCAN_B  1024
#define SCAN_NB ((N_NODES + SCAN_B - 1) / SCAN_B)   // 49

// Scratch (no allocations allowed)
__device__ __half g_x16[N_NODES * D];
__device__ __half g_z116[N_NODES * D];
__device__ __half g_h16[N_NODES * D];
__device__ __half g_z216[N_NODES * D];
__device__ __half g_w1a16[D * D];
__device__ __half g_w1b16[D * D];
__device__ __half g_w2a16[D * H2];
__device__ __half g_w2b16[H2 * H2];
// meta: [0, N_NODES) deg ; [N_NODES, +64) bsum ; [N_NODES+64, +128) flags
__device__ int    g_meta[N_NODES + 128];
__device__ int    g_rowptr[N_NODES + 1];
__device__ int    g_rank[N_EDGES];
__device__ int    g_ebuf[N_EDGES];

// ---------------- converts ----------------
__global__ void k_cvt(const float* __restrict__ x, __half* __restrict__ x16, int n4) {
    int i = blockIdx.x * blockDim.x + threadIdx.x;
    if (i < n4) {
        float4 v = reinterpret_cast<const float4*>(x)[i];
        __half2 p0 = __floats2half2_rn(v.x, v.y);
        __half2 p1 = __floats2half2_rn(v.z, v.w);
        uint2 st;
        st.x = *reinterpret_cast<unsigned*>(&p0);
        st.y = *reinterpret_cast<unsigned*>(&p1);
        reinterpret_cast<uint2*>(x16)[i] = st;
    }
}

__global__ void k_cvtw(const float* __restrict__ Wa, const float* __restrict__ Wb,
                       const float* __restrict__ W2a, const float* __restrict__ W2b,
                       __half* __restrict__ wa, __half* __restrict__ wb,
                       __half* __restrict__ w2a, __half* __restrict__ w2b) {
    int i = blockIdx.x * blockDim.x + threadIdx.x;
    if (i < D * D) {
        wa[i] = __float2half_rn(Wa[i]);
        wb[i] = __float2half_rn(Wb[i]);
    }
    if (i < D * H2)  w2a[i] = __float2half_rn(W2a[i]);
    if (i < H2 * H2) w2b[i] = __float2half_rn(W2b[i]);
}

// ---------------- CSR build ----------------
__global__ void k_hist(const int* __restrict__ ei, int* __restrict__ deg,
                       int* __restrict__ rank) {
    int e = blockIdx.x * blockDim.x + threadIdx.x;
    if (e < N_EDGES) rank[e] = atomicAdd(&deg[ei[N_EDGES + e]], 1);
}

__global__ __launch_bounds__(SCAN_B)
void k_scan_one(int* __restrict__ meta, int* __restrict__ rowptr) {
    const int* deg  = meta;
    int* bsum = meta + N_NODES;
    volatile int* flag = meta + N_NODES + 64;
    __shared__ int s[SCAN_B];
    __shared__ int bs[64];
    __shared__ int boff_s;
    int t = threadIdx.x;
    int i = blockIdx.x * SCAN_B + t;
    int v = (i < N_NODES) ? deg[i] : 0;
    s[t] = v;
    __syncthreads();
    for (int off = 1; off < SCAN_B; off <<= 1) {
        int add = (t >= off) ? s[t - off] : 0;
        __syncthreads();
        s[t] += add;
        __syncthreads();
    }
    if (t == SCAN_B - 1) {
        bsum[blockIdx.x] = s[t];
        __threadfence();
        flag[blockIdx.x] = 1;
    }
    if (t < SCAN_NB) {
        while (flag[t] == 0) { }
    }
    __syncthreads();
    if (t < SCAN_NB) bs[t] = bsum[t];
    __syncthreads();
    if (t == 0) {
        int o = 0;
        for (int b = 0; b < blockIdx.x; b++) o += bs[b];
        boff_s = o;
    }
    __syncthreads();
    if (i < N_NODES) rowptr[i] = s[t] - v + boff_s;
    if (i == 0) rowptr[N_NODES] = N_EDGES;
}

__global__ void k_fill(const int* __restrict__ ei, const int* __restrict__ rank,
                       const int* __restrict__ rowptr, int* __restrict__ ebuf) {
    int e = blockIdx.x * blockDim.x + threadIdx.x;
    if (e < N_EDGES) {
        int dst = ei[N_EDGES + e];
        ebuf[rowptr[dst] + rank[e]] = ei[e];
    }
}

// ---------------- paired-edge fp16 gather (fp16 in, fp16 out) ----------------
__device__ __forceinline__ void acc_h8(float* acc, uint4 r) {
    __half2* h = reinterpret_cast<__half2*>(&r);
    #pragma unroll
    for (int q = 0; q < 4; q++) {
        float2 f2 = __half22float2(h[q]);
        acc[2 * q + 0] += f2.x;
        acc[2 * q + 1] += f2.y;
    }
}

__global__ __launch_bounds__(256)
void k_gagg16(const __half* __restrict__ feat, const float* __restrict__ eps,
              const int* __restrict__ rowptr, const int* __restrict__ ebuf,
              __half* __restrict__ z16) {
    int warp = (blockIdx.x * blockDim.x + threadIdx.x) >> 5;
    int lane = threadIdx.x & 31;
    if (warp >= N_NODES) return;
    int beg = rowptr[warp];
    int end = rowptr[warp + 1];
    const uint4* f = reinterpret_cast<const uint4*>(feat);
    const bool act = lane < 24;
    const int  g   = (lane >= 12) ? 1 : 0;
    const int  gl  = lane - g * 12;

    float acc[8] = {0.f, 0.f, 0.f, 0.f, 0.f, 0.f, 0.f, 0.f};
    if (lane < 12) {
        float s = 1.0f + *eps;
        uint4 r = f[warp * CH16 + lane];
        __half2* h = reinterpret_cast<__half2*>(&r);
        #pragma unroll
        for (int q = 0; q < 4; q++) {
            float2 f2 = __half22float2(h[q]);
            acc[2 * q + 0] = s * f2.x;
            acc[2 * q + 1] = s * f2.y;
        }
    }
    for (int e0 = beg; e0 < end; e0 += 4) {
        int eA = e0 + g * 2;
        if (act && eA < end) {
            int s0 = __ldg(&ebuf[eA]);
            int s1 = (eA + 1 < end) ? __ldg(&ebuf[eA + 1]) : -1;
            uint4 r0 = f[s0 * CH16 + gl];
            acc_h8(acc, r0);
            if (s1 >= 0) {
                uint4 r1 = f[s1 * CH16 + gl];
                acc_h8(acc, r1);
            }
        }
    }
    #pragma unroll
    for (int q = 0; q < 8; q++)
        acc[q] += __shfl_down_sync(0xffffffffu, acc[q], 12);
    if (lane < 12) {
        __half2 p0 = __floats2half2_rn(acc[0], acc[1]);
        __half2 p1 = __floats2half2_rn(acc[2], acc[3]);
        __half2 p2 = __floats2half2_rn(acc[4], acc[5]);
        __half2 p3 = __floats2half2_rn(acc[6], acc[7]);
        uint4 st;
        st.x = *reinterpret_cast<unsigned*>(&p0);
        st.y = *reinterpret_cast<unsigned*>(&p1);
        st.z = *reinterpret_cast<unsigned*>(&p2);
        st.w = *reinterpret_cast<unsigned*>(&p3);
        reinterpret_cast<uint4*>(z16)[warp * CH16 + lane] = st;
    }
}

// ---------------- MLP1 via WMMA fp16 (proven R15 layout) ----------------
#define M1 64
__global__ __launch_bounds__(256)
void k_mlp1_w(const __half* __restrict__ z16,
              const __half* __restrict__ wa, const float* __restrict__ b1a,
              const __half* __restrict__ wb, const float* __restrict__ b1b,
              __half* __restrict__ h) {
    __shared__ __align__(16) char pool[43008];
    __half* As = reinterpret_cast<__half*>(pool);
    __half* Bs = reinterpret_cast<__half*>(pool + 12288);
    __half* Ts = reinterpret_cast<__half*>(pool + 30720);
    float*  Ct = reinterpret_cast<float*>(pool);
    const int tid = threadIdx.x;
    const int wid = tid >> 5;
    const int row0 = blockIdx.x * M1;
    const int strip = wid >> 1;
    const int cbase = (wid & 1) * 48;

    {
        uint4* Au = reinterpret_cast<uint4*>(As);
        const uint4* Zu = reinterpret_cast<const uint4*>(z16);
        for (int i = tid; i < M1 * CH16; i += 256) {
            int r = i / CH16;
            Au[i] = (row0 + r < N_NODES) ? Zu[(row0 + r) * CH16 + (i % CH16)]
                                         : make_uint4(0u, 0u, 0u, 0u);
        }
        uint4* Bu = reinterpret_cast<uint4*>(Bs);
        const uint4* Wu = reinterpret_cast<const uint4*>(wa);
        for (int i = tid; i < D * D / 8; i += 256) Bu[i] = Wu[i];
    }
    __syncthreads();

    wmma::fragment<wmma::accumulator, 16, 16, 16, float> acc[3];
    #pragma unroll
    for (int j = 0; j < 3; j++) wmma::fill_fragment(acc[j], 0.0f);
    #pragma unroll
    for (int k = 0; k < 6; k++) {
        wmma::fragment<wmma::matrix_a, 16, 16, 16, __half, wmma::row_major> a;
        wmma::load_matrix_sync(a, As + strip * 16 * D + k * 16, D);
        #pragma unroll
        for (int j = 0; j < 3; j++) {
            wmma::fragment<wmma::matrix_b, 16, 16, 16, __half, wmma::row_major> b;
            wmma::load_matrix_sync(b, Bs + (k * 16) * D + cbase + j * 16, D);
            wmma::mma_sync(acc[j], a, b, acc[j]);
        }
    }
    __syncthreads();
    #pragma unroll
    for (int j = 0; j < 3; j++)
        wmma::store_matrix_sync(Ct + strip * 16 * D + cbase + j * 16, acc[j], D,
                                wmma::mem_row_major);
    __syncthreads();

    for (int i = tid; i < M1 * CH16; i += 256) {
        int r = i / CH16, c0 = (i % CH16) * 8;
        float4 v0 = *reinterpret_cast<float4*>(&Ct[r * D + c0]);
        float4 v1 = *reinterpret_cast<float4*>(&Ct[r * D + c0 + 4]);
        float4 ba0 = *reinterpret_cast<const float4*>(&b1a[c0]);
        float4 ba1 = *reinterpret_cast<const float4*>(&b1a[c0 + 4]);
        __half2 p0 = __floats2half2_rn(fmaxf(v0.x + ba0.x, 0.f), fmaxf(v0.y + ba0.y, 0.f));
        __half2 p1 = __floats2half2_rn(fmaxf(v0.z + ba0.z, 0.f), fmaxf(v0.w + ba0.w, 0.f));
        __half2 p2 = __floats2half2_rn(fmaxf(v1.x + ba1.x, 0.f), fmaxf(v1.y + ba1.y, 0.f));
        __half2 p3 = __floats2half2_rn(fmaxf(v1.z + ba1.z, 0.f), fmaxf(v1.w + ba1.w, 0.f));
        uint4 st;
        st.x = *reinterpret_cast<unsigned*>(&p0);
        st.y = *reinterpret_cast<unsigned*>(&p1);
        st.z = *reinterpret_cast<unsigned*>(&p2);
        st.w = *reinterpret_cast<unsigned*>(&p3);
        reinterpret_cast<uint4*>(Ts)[i] = st;
    }
    __syncthreads();

    {
        uint4* Bu = reinterpret_cast<uint4*>(Bs);
        const uint4* Wu = reinterpret_cast<const uint4*>(wb);
        for (int i = tid; i < D * D / 8; i += 256) Bu[i] = Wu[i];
    }
    __syncthreads();

    #pragma unroll
    for (int j = 0; j < 3; j++) wmma::fill_fragment(acc[j], 0.0f);
    #pragma unroll
    for (int k = 0; k < 6; k++) {
        wmma::fragment<wmma::matrix_a, 16, 16, 16, __half, wmma::row_major> a;
        wmma::load_matrix_sync(a, Ts + strip * 16 * D + k * 16, D);
        #pragma unroll
        for (int j = 0; j < 3; j++) {
            wmma::fragment<wmma::matrix_b, 16, 16, 16, __half, wmma::row_major> b;
            wmma::load_matrix_sync(b, Bs + (k * 16) * D + cbase + j * 16, D);
            wmma::mma_sync(acc[j], a, b, acc[j]);
        }
    }
    __syncthreads();
    #pragma unroll
    for (int j = 0; j < 3; j++)
        wmma::store_matrix_sync(Ct + strip * 16 * D + cbase + j * 16, acc[j], D,
                                wmma::mem_row_major);
    __syncthreads();

    for (int i = tid; i < M1 * CH16; i += 256) {
        int r = i / CH16, c0 = (i % CH16) * 8;
        int row = row0 + r;
        if (row < N_NODES) {
            float4 v0 = *reinterpret_cast<float4*>(&Ct[r * D + c0]);
            float4 v1 = *reinterpret_cast<float4*>(&Ct[r * D + c0 + 4]);
            float4 bb0 = *reinterpret_cast<const float4*>(&b1b[c0]);
            float4 bb1 = *reinterpret_cast<const float4*>(&b1b[c0 + 4]);
            __half2 p0 = __floats2half2_rn(fmaxf(v0.x + bb0.x, 0.f), fmaxf(v0.y + bb0.y, 0.f));
            __half2 p1 = __floats2half2_rn(fmaxf(v0.z + bb0.z, 0.f), fmaxf(v0.w + bb0.w, 0.f));
            __half2 p2 = __floats2half2_rn(fmaxf(v1.x + bb1.x, 0.f), fmaxf(v1.y + bb1.y, 0.f));
            __half2 p3 = __floats2half2_rn(fmaxf(v1.z + bb1.z, 0.f), fmaxf(v1.w + bb1.w, 0.f));
            uint4 st;
            st.x = *reinterpret_cast<unsigned*>(&p0);
            st.y = *reinterpret_cast<unsigned*>(&p1);
            st.z = *reinterpret_cast<unsigned*>(&p2);
            st.w = *reinterpret_cast<unsigned*>(&p3);
            *reinterpret_cast<uint4*>(&h[(long long)row * D + c0]) = st;
        }
    }
}

// ---------------- MLP2 + head via WMMA fp16 (separate arrays, NO aliasing) ----
#define M2 64
__global__ __launch_bounds__(256)
void k_mlp2_w(const __half* __restrict__ z16,
              const __half* __restrict__ w2a, const float* __restrict__ b2a,
              const __half* __restrict__ w2b, const float* __restrict__ b2b,
              const float* __restrict__ Wh,  const float* __restrict__ bh,
              float* __restrict__ out) {
    __shared__ __align__(16) __half As[M2 * D];       // 12288 B
    __shared__ __align__(16) __half B1s[D * H2];      // 6144 B
    __shared__ __align__(16) __half B2s[H2 * H2];     // 2048 B
    __shared__ __align__(16) float  Ct[M2 * H2];      // 8192 B
    __shared__ __align__(16) __half Ts[M2 * H2];      // 4096 B
    __shared__ float Wh_s[H2 * OUTD];                 // 512 B
    __shared__ float b2a_s[H2], b2b_s[H2], bh_s[OUTD];
    const int tid = threadIdx.x;
    const int wid = tid >> 5;
    const int row0 = blockIdx.x * M2;
    const int strip = wid >> 1;           // 0..3 (16 rows each)
    const int ch = (wid & 1) * 16;        // col 0 or 16

    // stage
    {
        uint4* Au = reinterpret_cast<uint4*>(As);
        const uint4* Zu = reinterpret_cast<const uint4*>(z16);
        for (int i = tid; i < M2 * CH16; i += 256) {
            int r = i / CH16;
            Au[i] = (row0 + r < N_NODES) ? Zu[(row0 + r) * CH16 + (i % CH16)]
                                         : make_uint4(0u, 0u, 0u, 0u);
        }
        uint4* B1u = reinterpret_cast<uint4*>(B1s);
        const uint4* W1u = reinterpret_cast<const uint4*>(w2a);
        for (int i = tid; i < D * H2 / 8; i += 256) B1u[i] = W1u[i];
        uint4* B2u = reinterpret_cast<uint4*>(B2s);
        const uint4* W2u = reinterpret_cast<const uint4*>(w2b);
        for (int i = tid; i < H2 * H2 / 8; i += 256) B2u[i] = W2u[i];
        if (tid < H2 * OUTD) Wh_s[tid] = Wh[tid];
        if (tid < H2) { b2a_s[tid] = b2a[tid]; b2b_s[tid] = b2b[tid]; }
        if (tid < OUTD) bh_s[tid] = bh[tid];
    }
    __syncthreads();

    // matmul1: C = z @ W2a   (64x96 @ 96x32), each warp one 16x16 C tile
    wmma::fragment<wmma::accumulator, 16, 16, 16, float> acc;
    wmma::fill_fragment(acc, 0.0f);
    #pragma unroll
    for (int k = 0; k < 6; k++) {
        wmma::fragment<wmma::matrix_a, 16, 16, 16, __half, wmma::row_major> a;
        wmma::load_matrix_sync(a, As + strip * 16 * D + k * 16, D);
        wmma::fragment<wmma::matrix_b, 16, 16, 16, __half, wmma::row_major> b;
        wmma::load_matrix_sync(b, B1s + (k * 16) * H2 + ch, H2);
        wmma::mma_sync(acc, a, b, acc);
    }
    wmma::store_matrix_sync(Ct + strip * 16 * H2 + ch, acc, H2, wmma::mem_row_major);
    __syncthreads();

    // epilogue1: t = fp16(relu(C + b2a)) -> Ts   (64x32 = 256 uint4 chunks)
    {
        int r = tid / 4, cq = (tid % 4) * 8;
        float4 v0 = *reinterpret_cast<float4*>(&Ct[r * H2 + cq]);
        float4 v1 = *reinterpret_cast<float4*>(&Ct[r * H2 + cq + 4]);
        float4 ba0 = make_float4(b2a_s[cq+0], b2a_s[cq+1], b2a_s[cq+2], b2a_s[cq+3]);
        float4 ba1 = make_float4(b2a_s[cq+4], b2a_s[cq+5], b2a_s[cq+6], b2a_s[cq+7]);
        __half2 p0 = __floats2half2_rn(fmaxf(v0.x + ba0.x, 0.f), fmaxf(v0.y + ba0.y, 0.f));
        __half2 p1 = __floats2half2_rn(fmaxf(v0.z + ba0.z, 0.f), fmaxf(v0.w + ba0.w, 0.f));
        __half2 p2 = __floats2half2_rn(fmaxf(v1.x + ba1.x, 0.f), fmaxf(v1.y + ba1.y, 0.f));
        __half2 p3 = __floats2half2_rn(fmaxf(v1.z + ba1.z, 0.f), fmaxf(v1.w + ba1.w, 0.f));
        uint4 st;
        st.x = *reinterpret_cast<unsigned*>(&p0);
        st.y = *reinterpret_cast<unsigned*>(&p1);
        st.z = *reinterpret_cast<unsigned*>(&p2);
        st.w = *reinterpret_cast<unsigned*>(&p3);
        *reinterpret_cast<uint4*>(&Ts[r * H2 + cq]) = st;
    }
    __syncthreads();

    // matmul2: C = t @ W2b   (64x32 @ 32x32)
    wmma::fill_fragment(acc, 0.0f);
    #pragma unroll
    for (int k = 0; k < 2; k++) {
        wmma::fragment<wmma::matrix_a, 16, 16, 16, __half, wmma::row_major> a;
        wmma::load_matrix_sync(a, Ts + strip * 16 * H2 + k * 16, H2);
        wmma::fragment<wmma::matrix_b, 16, 16, 16, __half, wmma::row_major> b;
        wmma::load_matrix_sync(b, B2s + (k * 16) * H2 + ch, H2);
        wmma::mma_sync(acc, a, b, acc);
    }
    __syncthreads();       // prior Ct reads (epilogue1) complete everywhere
    wmma::store_matrix_sync(Ct + strip * 16 * H2 + ch, acc, H2, wmma::mem_row_major);
    __syncthreads();

    // head: out[row] = relu(C + b2b) @ Wh + bh   (4 threads per row)
    {
        int r = tid >> 2;        // 0..63
        int o = tid & 3;
        int row = row0 + r;
        if (row < N_NODES) {
            float s = bh_s[o];
            #pragma unroll
            for (int k = 0; k < H2; k++) {
                float bv = fmaxf(Ct[r * H2 + k] + b2b_s[k], 0.f);
                s = fmaf(bv, Wh_s[k * OUTD + o], s);
            }
            out[(long long)row * OUTD + o] = s;
        }
    }
}

extern "C" void kernel_launch(void* const* d_in, const int* in_sizes, int n_in,
                              void* d_out, int out_size) {
    const float* x    = (const float*)d_in[0];
    const int*   ei   = (const int*)  d_in[1];
    const float* eps1 = (const float*)d_in[2];
    const float* eps2 = (const float*)d_in[3];
    const float* W1a  = (const float*)d_in[4];
    const float* b1a  = (const float*)d_in[5];
    const float* W1b  = (const float*)d_in[6];
    const float* b1b  = (const float*)d_in[7];
    const float* W2a  = (const float*)d_in[8];
    const float* b2a  = (const float*)d_in[9];
    const float* W2b  = (const float*)d_in[10];
    const float* b2b  = (const float*)d_in[11];
    const float* Wh   = (const float*)d_in[12];
    const float* bh   = (const float*)d_in[13];
    float* out = (float*)d_out;

    __half *x16, *z116, *h16, *z216, *wa16, *wb16, *w2a16, *w2b16;
    int *meta, *rowptr, *rank, *ebuf;
    cudaGetSymbolAddress((void**)&x16, g_x16);
    cudaGetSymbolAddress((void**)&z116, g_z116);
    cudaGetSymbolAddress((void**)&h16, g_h16);
    cudaGetSymbolAddress((void**)&z216, g_z216);
    cudaGetSymbolAddress((void**)&wa16, g_w1a16);
    cudaGetSymbolAddress((void**)&wb16, g_w1b16);
    cudaGetSymbolAddress((void**)&w2a16, g_w2a16);
    cudaGetSymbolAddress((void**)&w2b16, g_w2b16);
    cudaGetSymbolAddress((void**)&meta, g_meta);
    cudaGetSymbolAddress((void**)&rowptr, g_rowptr);
    cudaGetSymbolAddress((void**)&rank, g_rank);
    cudaGetSymbolAddress((void**)&ebuf, g_ebuf);

    const int eb = (N_EDGES + 255) / 256;
    const int n4 = N_NODES * D / 4;
    const int cvt_blocks  = (n4 + 255) / 256;
    const int cvtw_blocks = (D * D + 255) / 256;
    const int gagg_blocks = (N_NODES * 32 + 255) / 256;
    const int mlp1_blocks = (N_NODES + M1 - 1) / M1;
    const int mlp2_blocks = (N_NODES + M2 - 1) / M2;

    // converts (independent of CSR)
    k_cvt<<<cvt_blocks, 256>>>(x, x16, n4);
    k_cvtw<<<cvtw_blocks, 256>>>(W1a, W1b, W2a, W2b, wa16, wb16, w2a16, w2b16);

    // CSR build
    cudaMemsetAsync(meta, 0, (N_NODES + 128) * sizeof(int));
    k_hist<<<eb, 256>>>(ei, meta, rank);
    k_scan_one<<<SCAN_NB, SCAN_B>>>(meta, rowptr);
    k_fill<<<eb, 256>>>(ei, rank, rowptr, ebuf);

    // Layer 1
    k_gagg16<<<gagg_blocks, 256>>>(x16, eps1, rowptr, ebuf, z116);
    k_mlp1_w<<<mlp1_blocks, 256>>>(z116, wa16, b1a, wb16, b1b, h16);

    // Layer 2 (same gather kernel, fp16 end-to-end; WMMA MLP2 + head)
    k_gagg16<<<gagg_blocks, 256>>>(h16, eps2, rowptr, ebuf, z216);
    k_mlp2_w<<<mlp2_blocks, 256>>>(z216, w2a16, b2a, w2b16, b2b, Wh, bh, out);
}

// round 17
// speedup vs baseline: 1.7344x; 1.0077x over previous
#include <cuda_runtime.h>
#include <cuda_fp16.h>
#include <mma.h>
using namespace nvcuda;

#define N_NODES 50000
#define N_EDGES 800000
#define D       96
#define H2      32
#define OUTD    4
#define CH      (D/4)
#define CH16    (D/8)        // 12 uint4 chunks of real data per fp16 row
#define PADH    128          // padded row stride in halves (256 B, 2 aligned lines)
#define PADC    (PADH/8)     // 16 uint4 per padded row
#define SCAN_B  1024
#define SCAN_NB ((N_NODES + SCAN_B - 1) / SCAN_B)   // 49

// Scratch (no allocations allowed)
__device__ __half g_x16[N_NODES * PADH];    // padded (gather-read)
__device__ __half g_h16[N_NODES * PADH];    // padded (gather-read)
__device__ __half g_z116[N_NODES * D];      // packed (linear access only)
__device__ __half g_z216[N_NODES * D];      // packed
__device__ __half g_w1a16[D * D];
__device__ __half g_w1b16[D * D];
__device__ __half g_w2a16[D * H2];
__device__ __half g_w2b16[H2 * H2];
// meta: [0, N_NODES) deg ; [N_NODES, +64) bsum ; [N_NODES+64, +128) flags
__device__ int    g_meta[N_NODES + 128];
__device__ int    g_rowptr[N_NODES + 1];
__device__ int    g_rank[N_EDGES];
__device__ int    g_ebuf[N_EDGES];

// ---------------- merged convert: x -> padded fp16, weights -> fp16 ----------
__global__ void k_cvt_all(const float* __restrict__ x, __half* __restrict__ x16,
                          const float* __restrict__ Wa, const float* __restrict__ Wb,
                          const float* __restrict__ W2a, const float* __restrict__ W2b,
                          __half* __restrict__ wa, __half* __restrict__ wb,
                          __half* __restrict__ w2a, __half* __restrict__ w2b,
                          int n4) {
    int i = blockIdx.x * blockDim.x + threadIdx.x;
    if (i < n4) {   // n4 = N_NODES * 24 float4 chunks
        int row = i / CH;
        int kc  = i - row * CH;
        float4 v = reinterpret_cast<const float4*>(x)[i];
        __half2 p0 = __floats2half2_rn(v.x, v.y);
        __half2 p1 = __floats2half2_rn(v.z, v.w);
        uint2 st;
        st.x = *reinterpret_cast<unsigned*>(&p0);
        st.y = *reinterpret_cast<unsigned*>(&p1);
        reinterpret_cast<uint2*>(x16)[row * (PADH / 4) + kc] = st;
    }
    if (i < D * D) {
        wa[i] = __float2half_rn(Wa[i]);
        wb[i] = __float2half_rn(Wb[i]);
    }
    if (i < D * H2)  w2a[i] = __float2half_rn(W2a[i]);
    if (i < H2 * H2) w2b[i] = __float2half_rn(W2b[i]);
}

// ---------------- CSR build ----------------
__global__ void k_hist(const int* __restrict__ ei, int* __restrict__ deg,
                       int* __restrict__ rank) {
    int e = blockIdx.x * blockDim.x + threadIdx.x;
    if (e < N_EDGES) rank[e] = atomicAdd(&deg[ei[N_EDGES + e]], 1);
}

// single-kernel scan (shfl block scan, 2 barriers; flag-based cross-block)
__global__ __launch_bounds__(SCAN_B)
void k_scan_one(int* __restrict__ meta, int* __restrict__ rowptr) {
    const int* deg  = meta;
    int* bsum = meta + N_NODES;
    volatile int* flag = meta + N_NODES + 64;
    __shared__ int wsum[32];
    __shared__ int bs[64];
    __shared__ int boff_s;
    int t = threadIdx.x;
    int lane = t & 31;
    int w = t >> 5;
    int i = blockIdx.x * SCAN_B + t;
    int v = (i < N_NODES) ? deg[i] : 0;

    // inclusive warp scan
    int sc = v;
    #pragma unroll
    for (int off = 1; off < 32; off <<= 1) {
        int n = __shfl_up_sync(0xffffffffu, sc, off);
        if (lane >= off) sc += n;
    }
    if (lane == 31) wsum[w] = sc;
    __syncthreads();
    if (w == 0) {
        int ws = wsum[lane];
        int s2 = ws;
        #pragma unroll
        for (int off = 1; off < 32; off <<= 1) {
            int n = __shfl_up_sync(0xffffffffu, s2, off);
            if (lane >= off) s2 += n;
        }
        wsum[lane] = s2 - ws;            // exclusive warp offsets
        if (lane == 31) {                // block total
            bsum[blockIdx.x] = s2;
            __threadfence();
            flag[blockIdx.x] = 1;
        }
    }
    if (t < SCAN_NB) {
        while (flag[t] == 0) { }
    }
    __syncthreads();
    if (t < SCAN_NB) bs[t] = bsum[t];
    __syncthreads();
    if (t == 0) {
        int o = 0;
        for (int b = 0; b < blockIdx.x; b++) o += bs[b];
        boff_s = o;
    }
    __syncthreads();
    if (i < N_NODES) rowptr[i] = (sc - v) + wsum[w] + boff_s;
    if (i == 0) rowptr[N_NODES] = N_EDGES;
}

__global__ void k_fill(const int* __restrict__ ei, const int* __restrict__ rank,
                       const int* __restrict__ rowptr, int* __restrict__ ebuf) {
    int e = blockIdx.x * blockDim.x + threadIdx.x;
    if (e < N_EDGES) {
        int dst = ei[N_EDGES + e];
        ebuf[rowptr[dst] + rank[e]] = ei[e];
    }
}

// ---------------- paired-edge fp16 gather (padded-row in, packed fp16 out) ----
__device__ __forceinline__ void acc_h8(float* acc, uint4 r) {
    __half2* h = reinterpret_cast<__half2*>(&r);
    #pragma unroll
    for (int q = 0; q < 4; q++) {
        float2 f2 = __half22float2(h[q]);
        acc[2 * q + 0] += f2.x;
        acc[2 * q + 1] += f2.y;
    }
}

__global__ __launch_bounds__(256)
void k_gagg16(const __half* __restrict__ feat, const float* __restrict__ eps,
              const int* __restrict__ rowptr, const int* __restrict__ ebuf,
              __half* __restrict__ z16) {
    int warp = (blockIdx.x * blockDim.x + threadIdx.x) >> 5;
    int lane = threadIdx.x & 31;
    if (warp >= N_NODES) return;
    int beg = rowptr[warp];
    int end = rowptr[warp + 1];
    const uint4* f = reinterpret_cast<const uint4*>(feat);   // PADC per row
    const bool act = lane < 24;
    const int  g   = (lane >= 12) ? 1 : 0;
    const int  gl  = lane - g * 12;

    float acc[8] = {0.f, 0.f, 0.f, 0.f, 0.f, 0.f, 0.f, 0.f};
    if (lane < 12) {
        float s = 1.0f + *eps;
        uint4 r = f[warp * PADC + lane];
        __half2* h = reinterpret_cast<__half2*>(&r);
        #pragma unroll
        for (int q = 0; q < 4; q++) {
            float2 f2 = __half22float2(h[q]);
            acc[2 * q + 0] = s * f2.x;
            acc[2 * q + 1] = s * f2.y;
        }
    }
    for (int e0 = beg; e0 < end; e0 += 4) {
        int eA = e0 + g * 2;
        if (act && eA < end) {
            int s0 = __ldg(&ebuf[eA]);
            int s1 = (eA + 1 < end) ? __ldg(&ebuf[eA + 1]) : -1;
            uint4 r0 = f[s0 * PADC + gl];
            acc_h8(acc, r0);
            if (s1 >= 0) {
                uint4 r1 = f[s1 * PADC + gl];
                acc_h8(acc, r1);
            }
        }
    }
    #pragma unroll
    for (int q = 0; q < 8; q++)
        acc[q] += __shfl_down_sync(0xffffffffu, acc[q], 12);
    if (lane < 12) {
        __half2 p0 = __floats2half2_rn(acc[0], acc[1]);
        __half2 p1 = __floats2half2_rn(acc[2], acc[3]);
        __half2 p2 = __floats2half2_rn(acc[4], acc[5]);
        __half2 p3 = __floats2half2_rn(acc[6], acc[7]);
        uint4 st;
        st.x = *reinterpret_cast<unsigned*>(&p0);
        st.y = *reinterpret_cast<unsigned*>(&p1);
        st.z = *reinterpret_cast<unsigned*>(&p2);
        st.w = *reinterpret_cast<unsigned*>(&p3);
        reinterpret_cast<uint4*>(z16)[warp * CH16 + lane] = st;   // packed out
    }
}

// ---------------- MLP1 via WMMA fp16 (R15-proven; h stored padded) ----------
#define M1 64
__global__ __launch_bounds__(256)
void k_mlp1_w(const __half* __restrict__ z16,
              const __half* __restrict__ wa, const float* __restrict__ b1a,
              const __half* __restrict__ wb, const float* __restrict__ b1b,
              __half* __restrict__ h) {
    __shared__ __align__(16) char pool[43008];
    __half* As = reinterpret_cast<__half*>(pool);
    __half* Bs = reinterpret_cast<__half*>(pool + 12288);
    __half* Ts = reinterpret_cast<__half*>(pool + 30720);
    float*  Ct = reinterpret_cast<float*>(pool);
    const int tid = threadIdx.x;
    const int wid = tid >> 5;
    const int row0 = blockIdx.x * M1;
    const int strip = wid >> 1;
    const int cbase = (wid & 1) * 48;

    {
        uint4* Au = reinterpret_cast<uint4*>(As);
        const uint4* Zu = reinterpret_cast<const uint4*>(z16);
        for (int i = tid; i < M1 * CH16; i += 256) {
            int r = i / CH16;
            Au[i] = (row0 + r < N_NODES) ? Zu[(row0 + r) * CH16 + (i % CH16)]
                                         : make_uint4(0u, 0u, 0u, 0u);
        }
        uint4* Bu = reinterpret_cast<uint4*>(Bs);
        const uint4* Wu = reinterpret_cast<const uint4*>(wa);
        for (int i = tid; i < D * D / 8; i += 256) Bu[i] = Wu[i];
    }
    __syncthreads();

    wmma::fragment<wmma::accumulator, 16, 16, 16, float> acc[3];
    #pragma unroll
    for (int j = 0; j < 3; j++) wmma::fill_fragment(acc[j], 0.0f);
    #pragma unroll
    for (int k = 0; k < 6; k++) {
        wmma::fragment<wmma::matrix_a, 16, 16, 16, __half, wmma::row_major> a;
        wmma::load_matrix_sync(a, As + strip * 16 * D + k * 16, D);
        #pragma unroll
        for (int j = 0; j < 3; j++) {
            wmma::fragment<wmma::matrix_b, 16, 16, 16, __half, wmma::row_major> b;
            wmma::load_matrix_sync(b, Bs + (k * 16) * D + cbase + j * 16, D);
            wmma::mma_sync(acc[j], a, b, acc[j]);
        }
    }
    __syncthreads();
    #pragma unroll
    for (int j = 0; j < 3; j++)
        wmma::store_matrix_sync(Ct + strip * 16 * D + cbase + j * 16, acc[j], D,
                                wmma::mem_row_major);
    __syncthreads();

    for (int i = tid; i < M1 * CH16; i += 256) {
        int r = i / CH16, c0 = (i % CH16) * 8;
        float4 v0 = *reinterpret_cast<float4*>(&Ct[r * D + c0]);
        float4 v1 = *reinterpret_cast<float4*>(&Ct[r * D + c0 + 4]);
        float4 ba0 = *reinterpret_cast<const float4*>(&b1a[c0]);
        float4 ba1 = *reinterpret_cast<const float4*>(&b1a[c0 + 4]);
        __half2 p0 = __floats2half2_rn(fmaxf(v0.x + ba0.x, 0.f), fmaxf(v0.y + ba0.y, 0.f));
        __half2 p1 = __floats2half2_rn(fmaxf(v0.z + ba0.z, 0.f), fmaxf(v0.w + ba0.w, 0.f));
        __half2 p2 = __floats2half2_rn(fmaxf(v1.x + ba1.x, 0.f), fmaxf(v1.y + ba1.y, 0.f));
        __half2 p3 = __floats2half2_rn(fmaxf(v1.z + ba1.z, 0.f), fmaxf(v1.w + ba1.w, 0.f));
        uint4 st;
        st.x = *reinterpret_cast<unsigned*>(&p0);
        st.y = *reinterpret_cast<unsigned*>(&p1);
        st.z = *reinterpret_cast<unsigned*>(&p2);
        st.w = *reinterpret_cast<unsigned*>(&p3);
        reinterpret_cast<uint4*>(Ts)[i] = st;
    }
    __syncthreads();

    {
        uint4* Bu = reinterpret_cast<uint4*>(Bs);
        const uint4* Wu = reinterpret_cast<const uint4*>(wb);
        for (int i = tid; i < D * D / 8; i += 256) Bu[i] = Wu[i];
    }
    __syncthreads();

    #pragma unroll
    for (int j = 0; j < 3; j++) wmma::fill_fragment(acc[j], 0.0f);
    #pragma unroll
    for (int k = 0; k < 6; k++) {
        wmma::fragment<wmma::matrix_a, 16, 16, 16, __half, wmma::row_major> a;
        wmma::load_matrix_sync(a, Ts + strip * 16 * D + k * 16, D);
        #pragma unroll
        for (int j = 0; j < 3; j++) {
            wmma::fragment<wmma::matrix_b, 16, 16, 16, __half, wmma::row_major> b;
            wmma::load_matrix_sync(b, Bs + (k * 16) * D + cbase + j * 16, D);
            wmma::mma_sync(acc[j], a, b, acc[j]);
        }
    }
    __syncthreads();
    #pragma unroll
    for (int j = 0; j < 3; j++)
        wmma::store_matrix_sync(Ct + strip * 16 * D + cbase + j * 16, acc[j], D,
                                wmma::mem_row_major);
    __syncthreads();

    // epilogue 2: h = fp16(relu(C + b1b)) -> gmem, PADDED row stride
    for (int i = tid; i < M1 * CH16; i += 256) {
        int r = i / CH16, c0 = (i % CH16) * 8;
        int row = row0 + r;
        if (row < N_NODES) {
            float4 v0 = *reinterpret_cast<float4*>(&Ct[r * D + c0]);
            float4 v1 = *reinterpret_cast<float4*>(&Ct[r * D + c0 + 4]);
            float4 bb0 = *reinterpret_cast<const float4*>(&b1b[c0]);
            float4 bb1 = *reinterpret_cast<const float4*>(&b1b[c0 + 4]);
            __half2 p0 = __floats2half2_rn(fmaxf(v0.x + bb0.x, 0.f), fmaxf(v0.y + bb0.y, 0.f));
            __half2 p1 = __floats2half2_rn(fmaxf(v0.z + bb0.z, 0.f), fmaxf(v0.w + bb0.w, 0.f));
            __half2 p2 = __floats2half2_rn(fmaxf(v1.x + bb1.x, 0.f), fmaxf(v1.y + bb1.y, 0.f));
            __half2 p3 = __floats2half2_rn(fmaxf(v1.z + bb1.z, 0.f), fmaxf(v1.w + bb1.w, 0.f));
            uint4 st;
            st.x = *reinterpret_cast<unsigned*>(&p0);
            st.y = *reinterpret_cast<unsigned*>(&p1);
            st.z = *reinterpret_cast<unsigned*>(&p2);
            st.w = *reinterpret_cast<unsigned*>(&p3);
            *reinterpret_cast<uint4*>(&h[(long long)row * PADH + c0]) = st;
        }
    }
}

// ---------------- MLP2 + head via WMMA fp16 (R16-proven, packed z2 in) -------
#define M2 64
__global__ __launch_bounds__(256)
void k_mlp2_w(const __half* __restrict__ z16,
              const __half* __restrict__ w2a, const float* __restrict__ b2a,
              const __half* __restrict__ w2b, const float* __restrict__ b2b,
              const float* __restrict__ Wh,  const float* __restrict__ bh,
              float* __restrict__ out) {
    __shared__ __align__(16) __half As[M2 * D];
    __shared__ __align__(16) __half B1s[D * H2];
    __shared__ __align__(16) __half B2s[H2 * H2];
    __shared__ __align__(16) float  Ct[M2 * H2];
    __shared__ __align__(16) __half Ts[M2 * H2];
    __shared__ float Wh_s[H2 * OUTD];
    __shared__ float b2a_s[H2], b2b_s[H2], bh_s[OUTD];
    const int tid = threadIdx.x;
    const int wid = tid >> 5;
    const int row0 = blockIdx.x * M2;
    const int strip = wid >> 1;
    const int ch = (wid & 1) * 16;

    {
        uint4* Au = reinterpret_cast<uint4*>(As);
        const uint4* Zu = reinterpret_cast<const uint4*>(z16);
        for (int i = tid; i < M2 * CH16; i += 256) {
            int r = i / CH16;
            Au[i] = (row0 + r < N_NODES) ? Zu[(row0 + r) * CH16 + (i % CH16)]
                                         : make_uint4(0u, 0u, 0u, 0u);
        }
        uint4* B1u = reinterpret_cast<uint4*>(B1s);
        const uint4* W1u = reinterpret_cast<const uint4*>(w2a);
        for (int i = tid; i < D * H2 / 8; i += 256) B1u[i] = W1u[i];
        uint4* B2u = reinterpret_cast<uint4*>(B2s);
        const uint4* W2u = reinterpret_cast<const uint4*>(w2b);
        for (int i = tid; i < H2 * H2 / 8; i += 256) B2u[i] = W2u[i];
        if (tid < H2 * OUTD) Wh_s[tid] = Wh[tid];
        if (tid < H2) { b2a_s[tid] = b2a[tid]; b2b_s[tid] = b2b[tid]; }
        if (tid < OUTD) bh_s[tid] = bh[tid];
    }
    __syncthreads();

    wmma::fragment<wmma::accumulator, 16, 16, 16, float> acc;
    wmma::fill_fragment(acc, 0.0f);
    #pragma unroll
    for (int k = 0; k < 6; k++) {
        wmma::fragment<wmma::matrix_a, 16, 16, 16, __half, wmma::row_major> a;
        wmma::load_matrix_sync(a, As + strip * 16 * D + k * 16, D);
        wmma::fragment<wmma::matrix_b, 16, 16, 16, __half, wmma::row_major> b;
        wmma::load_matrix_sync(b, B1s + (k * 16) * H2 + ch, H2);
        wmma::mma_sync(acc, a, b, acc);
    }
    wmma::store_matrix_sync(Ct + strip * 16 * H2 + ch, acc, H2, wmma::mem_row_major);
    __syncthreads();

    {
        int r = tid / 4, cq = (tid % 4) * 8;
        float4 v0 = *reinterpret_cast<float4*>(&Ct[r * H2 + cq]);
        float4 v1 = *reinterpret_cast<float4*>(&Ct[r * H2 + cq + 4]);
        float4 ba0 = make_float4(b2a_s[cq+0], b2a_s[cq+1], b2a_s[cq+2], b2a_s[cq+3]);
        float4 ba1 = make_float4(b2a_s[cq+4], b2a_s[cq+5], b2a_s[cq+6], b2a_s[cq+7]);
        __half2 p0 = __floats2half2_rn(fmaxf(v0.x + ba0.x, 0.f), fmaxf(v0.y + ba0.y, 0.f));
        __half2 p1 = __floats2half2_rn(fmaxf(v0.z + ba0.z, 0.f), fmaxf(v0.w + ba0.w, 0.f));
        __half2 p2 = __floats2half2_rn(fmaxf(v1.x + ba1.x, 0.f), fmaxf(v1.y + ba1.y, 0.f));
        __half2 p3 = __floats2half2_rn(fmaxf(v1.z + ba1.z, 0.f), fmaxf(v1.w + ba1.w, 0.f));
        uint4 st;
        st.x = *reinterpret_cast<unsigned*>(&p0);
        st.y = *reinterpret_cast<unsigned*>(&p1);
        st.z = *reinterpret_cast<unsigned*>(&p2);
        st.w = *reinterpret_cast<unsigned*>(&p3);
        *reinterpret_cast<uint4*>(&Ts[r * H2 + cq]) = st;
    }
    __syncthreads();

    wmma::fill_fragment(acc, 0.0f);
    #pragma unroll
    for (int k = 0; k < 2; k++) {
        wmma::fragment<wmma::matrix_a, 16, 16, 16, __half, wmma::row_major> a;
        wmma::load_matrix_sync(a, Ts + strip * 16 * H2 + k * 16, H2);
        wmma::fragment<wmma::matrix_b, 16, 16, 16, __half, wmma::row_major> b;
        wmma::load_matrix_sync(b, B2s + (k * 16) * H2 + ch, H2);
        wmma::mma_sync(acc, a, b, acc);
    }
    __syncthreads();
    wmma::store_matrix_sync(Ct + strip * 16 * H2 + ch, acc, H2, wmma::mem_row_major);
    __syncthreads();

    {
        int r = tid >> 2;
        int o = tid & 3;
        int row = row0 + r;
        if (row < N_NODES) {
            float s = bh_s[o];
            #pragma unroll
            for (int k = 0; k < H2; k++) {
                float bv = fmaxf(Ct[r * H2 + k] + b2b_s[k], 0.f);
                s = fmaf(bv, Wh_s[k * OUTD + o], s);
            }
            out[(long long)row * OUTD + o] = s;
        }
    }
}

extern "C" void kernel_launch(void* const* d_in, const int* in_sizes, int n_in,
                              void* d_out, int out_size) {
    const float* x    = (const float*)d_in[0];
    const int*   ei   = (const int*)  d_in[1];
    const float* eps1 = (const float*)d_in[2];
    const float* eps2 = (const float*)d_in[3];
    const float* W1a  = (const float*)d_in[4];
    const float* b1a  = (const float*)d_in[5];
    const float* W1b  = (const float*)d_in[6];
    const float* b1b  = (const float*)d_in[7];
    const float* W2a  = (const float*)d_in[8];
    const float* b2a  = (const float*)d_in[9];
    const float* W2b  = (const float*)d_in[10];
    const float* b2b  = (const float*)d_in[11];
    const float* Wh   = (const float*)d_in[12];
    const float* bh   = (const float*)d_in[13];
    float* out = (float*)d_out;

    __half *x16, *h16, *z116, *z216, *wa16, *wb16, *w2a16, *w2b16;
    int *meta, *rowptr, *rank, *ebuf;
    cudaGetSymbolAddress((void**)&x16, g_x16);
    cudaGetSymbolAddress((void**)&h16, g_h16);
    cudaGetSymbolAddress((void**)&z116, g_z116);
    cudaGetSymbolAddress((void**)&z216, g_z216);
    cudaGetSymbolAddress((void**)&wa16, g_w1a16);
    cudaGetSymbolAddress((void**)&wb16, g_w1b16);
    cudaGetSymbolAddress((void**)&w2a16, g_w2a16);
    cudaGetSymbolAddress((void**)&w2b16, g_w2b16);
    cudaGetSymbolAddress((void**)&meta, g_meta);
    cudaGetSymbolAddress((void**)&rowptr, g_rowptr);
    cudaGetSymbolAddress((void**)&rank, g_rank);
    cudaGetSymbolAddress((void**)&ebuf, g_ebuf);

    const int eb = (N_EDGES + 255) / 256;
    const int n4 = N_NODES * CH;
    const int cvt_blocks  = (n4 + 255) / 256;
    const int gagg_blocks = (N_NODES * 32 + 255) / 256;
    const int mlp1_blocks = (N_NODES + M1 - 1) / M1;
    const int mlp2_blocks = (N_NODES + M2 - 1) / M2;

    // merged converts (independent of CSR)
    k_cvt_all<<<cvt_blocks, 256>>>(x, x16, W1a, W1b, W2a, W2b,
                                   wa16, wb16, w2a16, w2b16, n4);

    // CSR build
    cudaMemsetAsync(meta, 0, (N_NODES + 128) * sizeof(int));
    k_hist<<<eb, 256>>>(ei, meta, rank);
    k_scan_one<<<SCAN_NB, SCAN_B>>>(meta, rowptr);
    k_fill<<<eb, 256>>>(ei, rank, rowptr, ebuf);

    // Layer 1: padded gather -> WMMA MLP (h stored padded)
    k_gagg16<<<gagg_blocks, 256>>>(x16, eps1, rowptr, ebuf, z116);
    k_mlp1_w<<<mlp1_blocks, 256>>>(z116, wa16, b1a, wb16, b1b, h16);

    // Layer 2: padded gather -> WMMA MLP2 + head
    k_gagg16<<<gagg_blocks, 256>>>(h16, eps2, rowptr, ebuf, z216);
    k_mlp2_w<<<mlp2_blocks, 256>>>(z216, w2a16, b2a, w2b16, b2b, Wh, bh, out);
}